// round 6
// baseline (speedup 1.0000x reference)
#include <cuda_runtime.h>
#include <cuda_bf16.h>

#define BATCH 4
#define TT    1024
#define DD    1024
#define HH    8
#define DKK   128
#define PP    2047
#define MHS   (BATCH*TT)
#define BK    32
#define BKP   40   // padded smem row (halves): conflict-free fragment banks

// ---------------- scratch (device globals; ushort = raw bf16) ---------------
__device__ unsigned short g_hshi[MHS*DD],  g_hslo[MHS*DD];
__device__ unsigned short g_pehi[PP*DD],   g_pelo[PP*DD];
__device__ unsigned short g_Wqhi[DD*DD],   g_Wqlo[DD*DD];
__device__ unsigned short g_Wkhi[DD*DD],   g_Wklo[DD*DD];
__device__ unsigned short g_Wvhi[DD*DD],   g_Wvlo[DD*DD];
__device__ unsigned short g_Wohi[DD*DD],   g_Wolo[DD*DD];
__device__ unsigned short g_Wphi[DD*DD],   g_Wplo[DD*DD];
__device__ unsigned short g_quhi[BATCH*HH*TT*DKK], g_qulo[BATCH*HH*TT*DKK];
__device__ unsigned short g_qvhi[BATCH*HH*TT*DKK], g_qvlo[BATCH*HH*TT*DKK];
__device__ unsigned short g_khi [BATCH*HH*TT*DKK], g_klo [BATCH*HH*TT*DKK];
__device__ unsigned short g_vThi[BATCH*HH*DKK*TT], g_vTlo[BATCH*HH*DKK*TT]; // (b,h,d,t)
__device__ unsigned short g_phi [HH*PP*DKK],       g_plo [HH*PP*DKK];
__device__ unsigned short g_athi[(size_t)BATCH*HH*TT*TT], g_atlo[(size_t)BATCH*HH*TT*TT];
__device__ unsigned short g_ohi [MHS*DD],  g_olo [MHS*DD];
__device__ float g_scores[(size_t)BATCH*HH*TT*TT]; // 134 MB fp32

typedef const __nv_bfloat16* bfp;

// ---------------- helpers ---------------------------------------------------
__device__ __forceinline__ void split2(float x, unsigned short& h, unsigned short& l)
{
    __nv_bfloat16 hb = __float2bfloat16_rn(x);
    float hf = __bfloat162float(hb);
    __nv_bfloat16 lb = __float2bfloat16_rn(x - hf);
    h = __bfloat16_as_ushort(hb);
    l = __bfloat16_as_ushort(lb);
}

#define MMA_BF16(D, A, B0, B1)                                             \
    asm volatile("mma.sync.aligned.m16n8k16.row.col.f32.bf16.bf16.f32 "    \
                 "{%0,%1,%2,%3}, {%4,%5,%6,%7}, {%8,%9}, {%0,%1,%2,%3};"   \
                 : "+f"(D[0]), "+f"(D[1]), "+f"(D[2]), "+f"(D[3])          \
                 : "r"(A[0]), "r"(A[1]), "r"(A[2]), "r"(A[3]),             \
                   "r"(B0), "r"(B1))

// ---------------- split-precision NT mainloop: C = A(MxK)*B(NxK)^T ----------
// 128x128 block tile, 256 threads (8 warps, each 32x64), BK=32.
// hi*hi + hi*lo + lo*hi (lo*lo dropped, ~2^-16 relative).
__device__ __forceinline__ void bmma_main(
    bfp Ahi, bfp Alo, int M,
    bfp Bhi, bfp Blo, int N,
    int K, int row0, int col0, float acc[2][8][4])
{
    __shared__ __align__(16) __nv_bfloat16 sAh[128][BKP];
    __shared__ __align__(16) __nv_bfloat16 sAl[128][BKP];
    __shared__ __align__(16) __nv_bfloat16 sBh[128][BKP];
    __shared__ __align__(16) __nv_bfloat16 sBl[128][BKP];

    const int tid  = threadIdx.x;
    const int lane = tid & 31, warp = tid >> 5;
    const int grp  = lane >> 2, qid = lane & 3;
    const int wm   = warp >> 1, wn = warp & 1;
    const int lr   = tid >> 2;       // 0..63 (tile row for loads)
    const int seg  = tid & 3;        // 8-half segment within BK

    for (int k0 = 0; k0 < K; k0 += BK) {
        #pragma unroll
        for (int half = 0; half < 2; half++) {
            int r  = lr + half * 64;
            int gk = k0 + seg * 8;
            uint4 z4 = make_uint4(0u, 0u, 0u, 0u);
            uint4 vah = z4, valo = z4, vbh = z4, vblo = z4;
            int ga = row0 + r;
            if (ga < M) {
                size_t off = (size_t)ga * K + gk;
                vah  = *reinterpret_cast<const uint4*>(Ahi + off);
                valo = *reinterpret_cast<const uint4*>(Alo + off);
            }
            int gb = col0 + r;
            if (gb < N) {
                size_t off = (size_t)gb * K + gk;
                vbh  = *reinterpret_cast<const uint4*>(Bhi + off);
                vblo = *reinterpret_cast<const uint4*>(Blo + off);
            }
            *reinterpret_cast<uint4*>(&sAh[r][seg*8]) = vah;
            *reinterpret_cast<uint4*>(&sAl[r][seg*8]) = valo;
            *reinterpret_cast<uint4*>(&sBh[r][seg*8]) = vbh;
            *reinterpret_cast<uint4*>(&sBl[r][seg*8]) = vblo;
        }
        __syncthreads();

        #pragma unroll
        for (int kb = 0; kb < BK; kb += 16) {
            unsigned ah[2][4], al[2][4];
            #pragma unroll
            for (int i = 0; i < 2; i++) {
                int ar = wm*32 + i*16 + grp;
                int ac_ = kb + qid*2;
                ah[i][0] = *(const unsigned*)&sAh[ar  ][ac_  ];
                ah[i][1] = *(const unsigned*)&sAh[ar+8][ac_  ];
                ah[i][2] = *(const unsigned*)&sAh[ar  ][ac_+8];
                ah[i][3] = *(const unsigned*)&sAh[ar+8][ac_+8];
                al[i][0] = *(const unsigned*)&sAl[ar  ][ac_  ];
                al[i][1] = *(const unsigned*)&sAl[ar+8][ac_  ];
                al[i][2] = *(const unsigned*)&sAl[ar  ][ac_+8];
                al[i][3] = *(const unsigned*)&sAl[ar+8][ac_+8];
            }
            #pragma unroll
            for (int j = 0; j < 8; j++) {
                int nr  = wn*64 + j*8 + grp;
                int nc_ = kb + qid*2;
                unsigned bh0 = *(const unsigned*)&sBh[nr][nc_  ];
                unsigned bh1 = *(const unsigned*)&sBh[nr][nc_+8];
                unsigned bl0 = *(const unsigned*)&sBl[nr][nc_  ];
                unsigned bl1 = *(const unsigned*)&sBl[nr][nc_+8];
                #pragma unroll
                for (int i = 0; i < 2; i++) {
                    MMA_BF16(acc[i][j], ah[i], bh0, bh1);
                    MMA_BF16(acc[i][j], ah[i], bl0, bl1);
                    MMA_BF16(acc[i][j], al[i], bh0, bh1);
                }
            }
        }
        __syncthreads();
    }
}

// epilogue coordinate helpers (per thread)
#define EPI_ROW(i, r)  (wm*32 + (i)*16 + grp + ((r) >> 1)*8)
#define EPI_COL(j, r)  (wn*64 + (j)*8 + qid*2 + ((r) & 1))
#define EPI_DECLS                                          \
    const int lane = threadIdx.x & 31;                     \
    const int warp = threadIdx.x >> 5;                     \
    const int grp = lane >> 2, qid = lane & 3;             \
    const int wm = warp >> 1, wn = warp & 1;

// ---------------- fp32 -> (hi,lo) bf16 split --------------------------------
__global__ void k_split(const float* __restrict__ src,
                        unsigned short* __restrict__ hi,
                        unsigned short* __restrict__ lo, int n)
{
    int i = blockIdx.x * blockDim.x + threadIdx.x;
    if (i < n) split2(src[i], hi[i], lo[i]);
}

// ---------------- Q/K/V projection ------------------------------------------
__global__ void __launch_bounds__(256, 1)
k_qkv(const float* __restrict__ bu, const float* __restrict__ bv)
{
    const int z = blockIdx.z;
    bfp Whi = (bfp)(z == 0 ? g_Wqhi : (z == 1 ? g_Wkhi : g_Wvhi));
    bfp Wlo = (bfp)(z == 0 ? g_Wqlo : (z == 1 ? g_Wklo : g_Wvlo));
    const int row0 = blockIdx.y * 128, col0 = blockIdx.x * 128;
    float acc[2][8][4] = {};
    bmma_main((bfp)g_hshi, (bfp)g_hslo, MHS, Whi, Wlo, DD, DD, row0, col0, acc);
    EPI_DECLS
    #pragma unroll
    for (int i = 0; i < 2; i++)
        #pragma unroll
        for (int j = 0; j < 8; j++)
            #pragma unroll
            for (int r = 0; r < 4; r++) {
                int m = row0 + EPI_ROW(i, r);
                int n = col0 + EPI_COL(j, r);
                int b = m >> 10, t = m & 1023;
                int h = n >> 7,  d = n & 127;
                float v = acc[i][j][r];
                size_t idx = ((size_t)(b*HH + h)*TT + t)*DKK + d;
                if (z == 0) {
                    split2(v + bu[h*DKK + d], g_quhi[idx], g_qulo[idx]);
                    split2(v + bv[h*DKK + d], g_qvhi[idx], g_qvlo[idx]);
                } else if (z == 1) {
                    split2(v, g_khi[idx], g_klo[idx]);
                } else {
                    size_t it = ((size_t)(b*HH + h)*DKK + d)*TT + t;  // transposed
                    split2(v, g_vThi[it], g_vTlo[it]);
                }
            }
}

// ---------------- P projection ----------------------------------------------
__global__ void __launch_bounds__(256, 1) k_p()
{
    const int row0 = blockIdx.y * 128, col0 = blockIdx.x * 128;
    float acc[2][8][4] = {};
    bmma_main((bfp)g_pehi, (bfp)g_pelo, PP, (bfp)g_Wphi, (bfp)g_Wplo, DD,
              DD, row0, col0, acc);
    EPI_DECLS
    #pragma unroll
    for (int i = 0; i < 2; i++)
        #pragma unroll
        for (int j = 0; j < 8; j++)
            #pragma unroll
            for (int r = 0; r < 4; r++) {
                int m = row0 + EPI_ROW(i, r);
                if (m >= PP) continue;
                int n = col0 + EPI_COL(j, r);
                int h = n >> 7, d = n & 127;
                size_t idx = ((size_t)h*PP + m)*DKK + d;
                split2(acc[i][j][r], g_phi[idx], g_plo[idx]);
            }
}

// ---------------- AC: scores = qu @ k^T per (b,h) ---------------------------
__global__ void __launch_bounds__(256, 1) k_ac()
{
    const int bh = blockIdx.z;
    const size_t ob = (size_t)bh * TT * DKK;
    const int row0 = blockIdx.y * 128, col0 = blockIdx.x * 128;
    float acc[2][8][4] = {};
    bmma_main((bfp)(g_quhi + ob), (bfp)(g_qulo + ob), TT,
              (bfp)(g_khi + ob),  (bfp)(g_klo + ob),  TT,
              DKK, row0, col0, acc);
    EPI_DECLS
    float* C = g_scores + (size_t)bh * TT * TT;
    #pragma unroll
    for (int i = 0; i < 2; i++)
        #pragma unroll
        for (int j = 0; j < 8; j++)
            #pragma unroll
            for (int r = 0; r < 4; r++) {
                int m = row0 + EPI_ROW(i, r);
                int n = col0 + EPI_COL(j, r);
                C[(size_t)m * TT + n] = acc[i][j][r];
            }
}

// ---------------- BD: scores[m, n+m-1023] += qv @ p^T (rel-shift fused) -----
__global__ void __launch_bounds__(256, 1) k_bd()
{
    const int bh = blockIdx.z, h = bh & 7;
    const int row0 = blockIdx.y * 128, col0 = blockIdx.x * 128;
    if (row0 + col0 + 254 < 1023 || row0 + col0 > 2046) return; // no k in [0,T)
    const size_t oa = (size_t)bh * TT * DKK;
    const size_t op = (size_t)h * PP * DKK;
    float acc[2][8][4] = {};
    bmma_main((bfp)(g_qvhi + oa), (bfp)(g_qvlo + oa), TT,
              (bfp)(g_phi + op),  (bfp)(g_plo + op),  PP,
              DKK, row0, col0, acc);
    EPI_DECLS
    float* C = g_scores + (size_t)bh * TT * TT;
    #pragma unroll
    for (int i = 0; i < 2; i++)
        #pragma unroll
        for (int j = 0; j < 8; j++)
            #pragma unroll
            for (int r = 0; r < 4; r++) {
                int m = row0 + EPI_ROW(i, r);
                int n = col0 + EPI_COL(j, r);
                if (n < PP) {
                    int k = n + m - 1023;
                    if (k >= 0 && k < TT)
                        C[(size_t)m * TT + k] += acc[i][j][r];
                }
            }
}

// ---------------- softmax: fp32 scores -> attn hi/lo bf16 -------------------
__global__ void k_softmax()
{
    const size_t rowoff = (size_t)blockIdx.x * TT;
    const float* r = g_scores + rowoff;
    const int tid = threadIdx.x;                 // 256 threads, float4 each
    float4 v = reinterpret_cast<const float4*>(r)[tid];
    const float s = 0.08838834764831845f;        // 1/sqrt(128)
    v.x *= s; v.y *= s; v.z *= s; v.w *= s;

    __shared__ float redm[8];
    __shared__ float reds[8];

    float m = fmaxf(fmaxf(v.x, v.y), fmaxf(v.z, v.w));
    #pragma unroll
    for (int o = 16; o > 0; o >>= 1) m = fmaxf(m, __shfl_xor_sync(~0u, m, o));
    if ((tid & 31) == 0) redm[tid >> 5] = m;
    __syncthreads();
    m = redm[0];
    #pragma unroll
    for (int w = 1; w < 8; w++) m = fmaxf(m, redm[w]);

    float4 e;
    e.x = __expf(v.x - m); e.y = __expf(v.y - m);
    e.z = __expf(v.z - m); e.w = __expf(v.w - m);
    float sum = e.x + e.y + e.z + e.w;
    #pragma unroll
    for (int o = 16; o > 0; o >>= 1) sum += __shfl_xor_sync(~0u, sum, o);
    if ((tid & 31) == 0) reds[tid >> 5] = sum;
    __syncthreads();
    sum = reds[0];
    #pragma unroll
    for (int w = 1; w < 8; w++) sum += reds[w];

    float inv = __frcp_rn(sum);
    float p0 = e.x*inv, p1 = e.y*inv, p2 = e.z*inv, p3 = e.w*inv;
    unsigned short h0,h1,h2,h3, l0,l1,l2,l3;
    split2(p0,h0,l0); split2(p1,h1,l1); split2(p2,h2,l2); split2(p3,h3,l3);
    size_t base = rowoff + (size_t)tid*4;
    uint2 ph = make_uint2((unsigned)h0 | ((unsigned)h1 << 16),
                          (unsigned)h2 | ((unsigned)h3 << 16));
    uint2 pl = make_uint2((unsigned)l0 | ((unsigned)l1 << 16),
                          (unsigned)l2 | ((unsigned)l3 << 16));
    *reinterpret_cast<uint2*>(&g_athi[base]) = ph;
    *reinterpret_cast<uint2*>(&g_atlo[base]) = pl;
}

// ---------------- AV: o = attn @ v per (b,h) (B = v^T, NT form) -------------
__global__ void __launch_bounds__(256, 1) k_av()
{
    const int bh = blockIdx.z, b = bh >> 3, h = bh & 7;
    const size_t oa = (size_t)bh * TT * TT;
    const size_t ov = (size_t)bh * DKK * TT;
    const int row0 = blockIdx.y * 128, col0 = 0;  // N = 128 fits one tile
    float acc[2][8][4] = {};
    bmma_main((bfp)(g_athi + oa), (bfp)(g_atlo + oa), TT,
              (bfp)(g_vThi + ov), (bfp)(g_vTlo + ov), DKK,
              TT, row0, col0, acc);
    EPI_DECLS
    #pragma unroll
    for (int i = 0; i < 2; i++)
        #pragma unroll
        for (int j = 0; j < 8; j++)
            #pragma unroll
            for (int r = 0; r < 4; r++) {
                int m = row0 + EPI_ROW(i, r);
                int n = EPI_COL(j, r);              // head-dim 0..127
                size_t idx = ((size_t)(b*TT + m)*HH + h)*DKK + n; // (b,t,h,d)
                split2(acc[i][j][r], g_ohi[idx], g_olo[idx]);
            }
}

// ---------------- output projection -----------------------------------------
__global__ void __launch_bounds__(256, 1) k_out(float* __restrict__ out)
{
    const int row0 = blockIdx.y * 128, col0 = blockIdx.x * 128;
    float acc[2][8][4] = {};
    bmma_main((bfp)g_ohi, (bfp)g_olo, MHS, (bfp)g_Wohi, (bfp)g_Wolo, DD,
              DD, row0, col0, acc);
    EPI_DECLS
    #pragma unroll
    for (int i = 0; i < 2; i++)
        #pragma unroll
        for (int j = 0; j < 8; j++)
            #pragma unroll
            for (int r = 0; r < 4; r++) {
                int m = row0 + EPI_ROW(i, r);
                int n = col0 + EPI_COL(j, r);
                out[(size_t)m * DD + n] = acc[i][j][r];
            }
}

// ---------------- launch ----------------------------------------------------
extern "C" void kernel_launch(void* const* d_in, const int* in_sizes, int n_in,
                              void* d_out, int out_size)
{
    const float* hs = (const float*)d_in[0];
    const float* pe = (const float*)d_in[1];
    const float* Wq = (const float*)d_in[2];
    const float* Wk = (const float*)d_in[3];
    const float* Wv = (const float*)d_in[4];
    const float* Wo = (const float*)d_in[5];
    const float* Wp = (const float*)d_in[6];
    const float* bu = (const float*)d_in[7];
    const float* bv = (const float*)d_in[8];
    float* out = (float*)d_out;

    unsigned short *hshi, *hslo, *pehi, *pelo;
    unsigned short *wqh, *wql, *wkh, *wkl, *wvh, *wvl, *woh, *wol, *wph, *wpl;
    cudaGetSymbolAddress((void**)&hshi, g_hshi); cudaGetSymbolAddress((void**)&hslo, g_hslo);
    cudaGetSymbolAddress((void**)&pehi, g_pehi); cudaGetSymbolAddress((void**)&pelo, g_pelo);
    cudaGetSymbolAddress((void**)&wqh, g_Wqhi);  cudaGetSymbolAddress((void**)&wql, g_Wqlo);
    cudaGetSymbolAddress((void**)&wkh, g_Wkhi);  cudaGetSymbolAddress((void**)&wkl, g_Wklo);
    cudaGetSymbolAddress((void**)&wvh, g_Wvhi);  cudaGetSymbolAddress((void**)&wvl, g_Wvlo);
    cudaGetSymbolAddress((void**)&woh, g_Wohi);  cudaGetSymbolAddress((void**)&wol, g_Wolo);
    cudaGetSymbolAddress((void**)&wph, g_Wphi);  cudaGetSymbolAddress((void**)&wpl, g_Wplo);

    k_split<<<(MHS*DD + 255)/256, 256>>>(hs, hshi, hslo, MHS*DD);
    k_split<<<(PP*DD + 255)/256, 256>>>(pe, pehi, pelo, PP*DD);
    k_split<<<(DD*DD + 255)/256, 256>>>(Wq, wqh, wql, DD*DD);
    k_split<<<(DD*DD + 255)/256, 256>>>(Wk, wkh, wkl, DD*DD);
    k_split<<<(DD*DD + 255)/256, 256>>>(Wv, wvh, wvl, DD*DD);
    k_split<<<(DD*DD + 255)/256, 256>>>(Wo, woh, wol, DD*DD);
    k_split<<<(DD*DD + 255)/256, 256>>>(Wp, wph, wpl, DD*DD);

    k_qkv<<<dim3(8, 32, 3), 256>>>(bu, bv);
    k_p  <<<dim3(8, 16), 256>>>();
    k_ac <<<dim3(8, 8, BATCH*HH), 256>>>();
    k_bd <<<dim3(16, 8, BATCH*HH), 256>>>();
    k_softmax<<<BATCH*HH*TT, 256>>>();
    k_av <<<dim3(1, 8, BATCH*HH), 256>>>();
    k_out<<<dim3(8, 32), 256>>>(out);
}

// round 8
// speedup vs baseline: 1.3727x; 1.3727x over previous
#include <cuda_runtime.h>
#include <cuda_bf16.h>
#include <stdint.h>

#define BATCH 4
#define TT    1024
#define DD    1024
#define HH    8
#define DKK   128
#define PP    2047
#define MHS   (BATCH*TT)
#define BK    32
#define ROWP  40                       // padded smem row stride (halves)
#define BUFP  (128*ROWP)               // halves per buffer
#define STAGEH (4*BUFP)                // halves per stage (Ahi,Alo,Bhi,Blo)
#define DYN_BYTES (2*STAGEH*2)         // 2 stages, bytes = 81920

// ---------------- scratch (device globals; ushort = raw bf16) ---------------
__device__ unsigned short g_hshi[MHS*DD],  g_hslo[MHS*DD];
__device__ unsigned short g_pehi[PP*DD],   g_pelo[PP*DD];
__device__ unsigned short g_Wqhi[DD*DD],   g_Wqlo[DD*DD];
__device__ unsigned short g_Wkhi[DD*DD],   g_Wklo[DD*DD];
__device__ unsigned short g_Wvhi[DD*DD],   g_Wvlo[DD*DD];
__device__ unsigned short g_Wohi[DD*DD],   g_Wolo[DD*DD];
__device__ unsigned short g_Wphi[DD*DD],   g_Wplo[DD*DD];
__device__ unsigned short g_quhi[BATCH*HH*TT*DKK], g_qulo[BATCH*HH*TT*DKK];
__device__ unsigned short g_qvhi[BATCH*HH*TT*DKK], g_qvlo[BATCH*HH*TT*DKK];
__device__ unsigned short g_khi [BATCH*HH*TT*DKK], g_klo [BATCH*HH*TT*DKK];
__device__ unsigned short g_vThi[BATCH*HH*DKK*TT], g_vTlo[BATCH*HH*DKK*TT]; // (b,h,d,t)
__device__ unsigned short g_phi [HH*PP*DKK],       g_plo [HH*PP*DKK];
__device__ unsigned short g_athi[(size_t)BATCH*HH*TT*TT], g_atlo[(size_t)BATCH*HH*TT*TT];
__device__ unsigned short g_ohi [MHS*DD],  g_olo [MHS*DD];
__device__ float g_scores[(size_t)BATCH*HH*TT*TT]; // 134 MB fp32

typedef const unsigned short* usp;

// ---------------- helpers ---------------------------------------------------
__device__ __forceinline__ void split2(float x, unsigned short& h, unsigned short& l)
{
    __nv_bfloat16 hb = __float2bfloat16_rn(x);
    float hf = __bfloat162float(hb);
    __nv_bfloat16 lb = __float2bfloat16_rn(x - hf);
    h = __bfloat16_as_ushort(hb);
    l = __bfloat16_as_ushort(lb);
}

__device__ __forceinline__ uint32_t cvta_s(const void* p)
{
    uint32_t a;
    asm("{ .reg .u64 t; cvta.to.shared.u64 t, %1; cvt.u32.u64 %0, t; }" : "=r"(a) : "l"(p));
    return a;
}

#define MMA_BF16(D, A, B0, B1)                                             \
    asm volatile("mma.sync.aligned.m16n8k16.row.col.f32.bf16.bf16.f32 "    \
                 "{%0,%1,%2,%3}, {%4,%5,%6,%7}, {%8,%9}, {%0,%1,%2,%3};"   \
                 : "+f"(D[0]), "+f"(D[1]), "+f"(D[2]), "+f"(D[3])          \
                 : "r"(A[0]), "r"(A[1]), "r"(A[2]), "r"(A[3]),             \
                   "r"(B0), "r"(B1))

#define LDSM4(R, addr)                                                          \
    asm volatile("ldmatrix.sync.aligned.m8n8.x4.shared.b16 {%0,%1,%2,%3}, [%4];"\
                 : "=r"((R)[0]), "=r"((R)[1]), "=r"((R)[2]), "=r"((R)[3])       \
                 : "r"(addr))

// ---------------- async stage loader ----------------------------------------
__device__ __forceinline__ void load_stage(unsigned short* sm, int s,
    usp Ahi, usp Alo, int M, usp Bhi, usp Blo, int N,
    int K, int row0, int col0, int k0)
{
    unsigned short* st = sm + s * STAGEH;
    const int tid = threadIdx.x;
    #pragma unroll
    for (int buf = 0; buf < 4; buf++) {
        usp src = (buf == 0) ? Ahi : (buf == 1) ? Alo : (buf == 2) ? Bhi : Blo;
        const int g0  = (buf < 2) ? row0 : col0;
        const int lim = (buf < 2) ? M    : N;
        unsigned short* db = st + buf * BUFP;
        #pragma unroll
        for (int t = 0; t < 2; t++) {
            int slot = tid + t * 256;          // 0..511
            int r = slot >> 2, seg = slot & 3;
            int g = g0 + r;
            int ok = (g < lim);
            const unsigned short* sp = src + (size_t)(ok ? g : 0) * K + k0 + seg * 8;
            uint32_t d = cvta_s(db + r * ROWP + seg * 8);
            asm volatile("cp.async.cg.shared.global [%0], [%1], 16, %2;"
                         :: "r"(d), "l"(sp), "r"(ok ? 16 : 0) : "memory");
        }
    }
}

// ---------------- split-precision NT mainloop: C = A(MxK)*B(NxK)^T ----------
// 128x128 tile, 256 threads (8 warps of 32x64), BK=32, cp.async 2-stage,
// ldmatrix fragments. hi*hi + hi*lo + lo*hi (lo*lo dropped).
__device__ __forceinline__ void bmma_main(
    usp Ahi, usp Alo, int M, usp Bhi, usp Blo, int N,
    int K, int row0, int col0, float acc[2][8][4])
{
    extern __shared__ unsigned short smv[];
    const int tid = threadIdx.x, lane = tid & 31, warp = tid >> 5;
    const int wm = warp >> 1, wn = warp & 1;
    const int mi = lane >> 3, lr8 = lane & 7;
    const int row_off = (mi & 1) * 8 + lr8;     // ldmatrix row within 16-grp
    const int col_off = (mi >> 1) * 8;          // ldmatrix k within 16

    const int niter = K >> 5;
    load_stage(smv, 0, Ahi, Alo, M, Bhi, Blo, N, K, row0, col0, 0);
    asm volatile("cp.async.commit_group;" ::: "memory");

    for (int it = 0; it < niter; it++) {
        if (it + 1 < niter) {
            load_stage(smv, (it + 1) & 1, Ahi, Alo, M, Bhi, Blo, N, K,
                       row0, col0, (it + 1) << 5);
            asm volatile("cp.async.commit_group;" ::: "memory");
            asm volatile("cp.async.wait_group 1;" ::: "memory");
        } else {
            asm volatile("cp.async.wait_group 0;" ::: "memory");
        }
        __syncthreads();

        const unsigned short* st = smv + (it & 1) * STAGEH;
        #pragma unroll
        for (int kb = 0; kb < BK; kb += 16) {
            uint32_t ah[2][4], al[2][4];
            #pragma unroll
            for (int i = 0; i < 2; i++) {
                int off = (wm * 32 + i * 16 + row_off) * ROWP + kb + col_off;
                LDSM4(ah[i], cvta_s(st + off));            // buf 0: A hi
                LDSM4(al[i], cvta_s(st + BUFP + off));     // buf 1: A lo
            }
            #pragma unroll
            for (int g = 0; g < 4; g++) {
                uint32_t bh4[4], bl4[4];
                int off = (wn * 64 + g * 16 + row_off) * ROWP + kb + col_off;
                LDSM4(bh4, cvta_s(st + 2 * BUFP + off));   // buf 2: B hi
                LDSM4(bl4, cvta_s(st + 3 * BUFP + off));   // buf 3: B lo
                #pragma unroll
                for (int i = 0; i < 2; i++) {
                    MMA_BF16(acc[i][g*2],   ah[i], bh4[0], bh4[2]);
                    MMA_BF16(acc[i][g*2],   ah[i], bl4[0], bl4[2]);
                    MMA_BF16(acc[i][g*2],   al[i], bh4[0], bh4[2]);
                    MMA_BF16(acc[i][g*2+1], ah[i], bh4[1], bh4[3]);
                    MMA_BF16(acc[i][g*2+1], ah[i], bl4[1], bl4[3]);
                    MMA_BF16(acc[i][g*2+1], al[i], bh4[1], bh4[3]);
                }
            }
        }
        __syncthreads();
    }
}

// epilogue coordinate helpers (per thread)
#define EPI_ROW(i, r)  (wm*32 + (i)*16 + grp + ((r) >> 1)*8)
#define EPI_COL(j, r)  (wn*64 + (j)*8 + qid*2 + ((r) & 1))
#define EPI_DECLS                                          \
    const int lane = threadIdx.x & 31;                     \
    const int warp = threadIdx.x >> 5;                     \
    const int grp = lane >> 2, qid = lane & 3;             \
    const int wm = warp >> 1, wn = warp & 1;

// ---------------- fp32 -> (hi,lo) bf16 split --------------------------------
__global__ void k_split(const float* __restrict__ src,
                        unsigned short* __restrict__ hi,
                        unsigned short* __restrict__ lo, int n)
{
    int i = blockIdx.x * blockDim.x + threadIdx.x;
    if (i < n) split2(src[i], hi[i], lo[i]);
}

// ---------------- Q/K/V projection ------------------------------------------
__global__ void __launch_bounds__(256, 2)
k_qkv(const float* __restrict__ bu, const float* __restrict__ bv)
{
    const int z = blockIdx.z;
    usp Whi = (z == 0) ? g_Wqhi : (z == 1) ? g_Wkhi : g_Wvhi;
    usp Wlo = (z == 0) ? g_Wqlo : (z == 1) ? g_Wklo : g_Wvlo;
    const int row0 = blockIdx.y * 128, col0 = blockIdx.x * 128;
    float acc[2][8][4] = {};
    bmma_main(g_hshi, g_hslo, MHS, Whi, Wlo, DD, DD, row0, col0, acc);
    EPI_DECLS
    #pragma unroll
    for (int i = 0; i < 2; i++)
        #pragma unroll
        for (int j = 0; j < 8; j++)
            #pragma unroll
            for (int r = 0; r < 4; r++) {
                int m = row0 + EPI_ROW(i, r);
                int n = col0 + EPI_COL(j, r);
                int b = m >> 10, t = m & 1023;
                int h = n >> 7,  d = n & 127;
                float v = acc[i][j][r];
                size_t idx = ((size_t)(b*HH + h)*TT + t)*DKK + d;
                if (z == 0) {
                    split2(v + bu[h*DKK + d], g_quhi[idx], g_qulo[idx]);
                    split2(v + bv[h*DKK + d], g_qvhi[idx], g_qvlo[idx]);
                } else if (z == 1) {
                    split2(v, g_khi[idx], g_klo[idx]);
                } else {
                    size_t it = ((size_t)(b*HH + h)*DKK + d)*TT + t;  // transposed
                    split2(v, g_vThi[it], g_vTlo[it]);
                }
            }
}

// ---------------- P projection ----------------------------------------------
__global__ void __launch_bounds__(256, 2) k_p()
{
    const int row0 = blockIdx.y * 128, col0 = blockIdx.x * 128;
    float acc[2][8][4] = {};
    bmma_main(g_pehi, g_pelo, PP, g_Wphi, g_Wplo, DD, DD, row0, col0, acc);
    EPI_DECLS
    #pragma unroll
    for (int i = 0; i < 2; i++)
        #pragma unroll
        for (int j = 0; j < 8; j++)
            #pragma unroll
            for (int r = 0; r < 4; r++) {
                int m = row0 + EPI_ROW(i, r);
                if (m >= PP) continue;
                int n = col0 + EPI_COL(j, r);
                int h = n >> 7, d = n & 127;
                size_t idx = ((size_t)h*PP + m)*DKK + d;
                split2(acc[i][j][r], g_phi[idx], g_plo[idx]);
            }
}

// ---------------- AC: scores = qu @ k^T per (b,h) ---------------------------
__global__ void __launch_bounds__(256, 2) k_ac()
{
    const int bh = blockIdx.z;
    const size_t ob = (size_t)bh * TT * DKK;
    const int row0 = blockIdx.y * 128, col0 = blockIdx.x * 128;
    float acc[2][8][4] = {};
    bmma_main(g_quhi + ob, g_qulo + ob, TT, g_khi + ob, g_klo + ob, TT,
              DKK, row0, col0, acc);
    EPI_DECLS
    float* C = g_scores + (size_t)bh * TT * TT;
    #pragma unroll
    for (int i = 0; i < 2; i++)
        #pragma unroll
        for (int j = 0; j < 8; j++)
            #pragma unroll
            for (int r = 0; r < 4; r++) {
                int m = row0 + EPI_ROW(i, r);
                int n = col0 + EPI_COL(j, r);
                C[(size_t)m * TT + n] = acc[i][j][r];
            }
}

// ---------------- BD: scores[m, n+m-1023] += qv @ p^T (rel-shift fused) -----
__global__ void __launch_bounds__(256, 2) k_bd()
{
    const int bh = blockIdx.z, h = bh & 7;
    const int row0 = blockIdx.y * 128, col0 = blockIdx.x * 128;
    if (row0 + col0 + 254 < 1023 || row0 + col0 > 2046) return; // no k in [0,T)
    const size_t oa = (size_t)bh * TT * DKK;
    const size_t op = (size_t)h * PP * DKK;
    float acc[2][8][4] = {};
    bmma_main(g_qvhi + oa, g_qvlo + oa, TT, g_phi + op, g_plo + op, PP,
              DKK, row0, col0, acc);
    EPI_DECLS
    float* C = g_scores + (size_t)bh * TT * TT;
    #pragma unroll
    for (int i = 0; i < 2; i++)
        #pragma unroll
        for (int j = 0; j < 8; j++)
            #pragma unroll
            for (int r = 0; r < 4; r++) {
                int m = row0 + EPI_ROW(i, r);
                int n = col0 + EPI_COL(j, r);
                if (n < PP) {
                    int k = n + m - 1023;
                    if ((unsigned)k < (unsigned)TT)
                        C[(size_t)m * TT + k] += acc[i][j][r];
                }
            }
}

// ---------------- softmax: fp32 scores -> attn hi/lo bf16 -------------------
__global__ void k_softmax()
{
    const size_t rowoff = (size_t)blockIdx.x * TT;
    const float* r = g_scores + rowoff;
    const int tid = threadIdx.x;                 // 256 threads, float4 each
    float4 v = reinterpret_cast<const float4*>(r)[tid];
    const float s = 0.08838834764831845f;        // 1/sqrt(128)
    v.x *= s; v.y *= s; v.z *= s; v.w *= s;

    __shared__ float redm[8];
    __shared__ float reds[8];

    float m = fmaxf(fmaxf(v.x, v.y), fmaxf(v.z, v.w));
    #pragma unroll
    for (int o = 16; o > 0; o >>= 1) m = fmaxf(m, __shfl_xor_sync(~0u, m, o));
    if ((tid & 31) == 0) redm[tid >> 5] = m;
    __syncthreads();
    m = redm[0];
    #pragma unroll
    for (int w = 1; w < 8; w++) m = fmaxf(m, redm[w]);

    float4 e;
    e.x = __expf(v.x - m); e.y = __expf(v.y - m);
    e.z = __expf(v.z - m); e.w = __expf(v.w - m);
    float sum = e.x + e.y + e.z + e.w;
    #pragma unroll
    for (int o = 16; o > 0; o >>= 1) sum += __shfl_xor_sync(~0u, sum, o);
    if ((tid & 31) == 0) reds[tid >> 5] = sum;
    __syncthreads();
    sum = reds[0];
    #pragma unroll
    for (int w = 1; w < 8; w++) sum += reds[w];

    float inv = __frcp_rn(sum);
    float p0 = e.x*inv, p1 = e.y*inv, p2 = e.z*inv, p3 = e.w*inv;
    unsigned short h0,h1,h2,h3, l0,l1,l2,l3;
    split2(p0,h0,l0); split2(p1,h1,l1); split2(p2,h2,l2); split2(p3,h3,l3);
    size_t base = rowoff + (size_t)tid*4;
    uint2 ph = make_uint2((unsigned)h0 | ((unsigned)h1 << 16),
                          (unsigned)h2 | ((unsigned)h3 << 16));
    uint2 pl = make_uint2((unsigned)l0 | ((unsigned)l1 << 16),
                          (unsigned)l2 | ((unsigned)l3 << 16));
    *reinterpret_cast<uint2*>(&g_athi[base]) = ph;
    *reinterpret_cast<uint2*>(&g_atlo[base]) = pl;
}

// ---------------- AV: o = attn @ v per (b,h) (B = vT, NT form) --------------
__global__ void __launch_bounds__(256, 2) k_av()
{
    const int bh = blockIdx.z, b = bh >> 3, h = bh & 7;
    const size_t oa = (size_t)bh * TT * TT;
    const size_t ov = (size_t)bh * DKK * TT;
    const int row0 = blockIdx.y * 128;
    float acc[2][8][4] = {};
    bmma_main(g_athi + oa, g_atlo + oa, TT, g_vThi + ov, g_vTlo + ov, DKK,
              TT, row0, 0, acc);
    EPI_DECLS
    #pragma unroll
    for (int i = 0; i < 2; i++)
        #pragma unroll
        for (int j = 0; j < 8; j++)
            #pragma unroll
            for (int r = 0; r < 4; r++) {
                int m = row0 + EPI_ROW(i, r);
                int n = EPI_COL(j, r);              // head-dim 0..127
                size_t idx = ((size_t)(b*TT + m)*HH + h)*DKK + n; // (b,t,h,d)
                split2(acc[i][j][r], g_ohi[idx], g_olo[idx]);
            }
}

// ---------------- output projection -----------------------------------------
__global__ void __launch_bounds__(256, 2) k_out(float* __restrict__ out)
{
    const int row0 = blockIdx.y * 128, col0 = blockIdx.x * 128;
    float acc[2][8][4] = {};
    bmma_main(g_ohi, g_olo, MHS, g_Wohi, g_Wolo, DD, DD, row0, col0, acc);
    EPI_DECLS
    #pragma unroll
    for (int i = 0; i < 2; i++)
        #pragma unroll
        for (int j = 0; j < 8; j++)
            #pragma unroll
            for (int r = 0; r < 4; r++) {
                int m = row0 + EPI_ROW(i, r);
                int n = col0 + EPI_COL(j, r);
                out[(size_t)m * DD + n] = acc[i][j][r];
            }
}

// ---------------- launch ----------------------------------------------------
extern "C" void kernel_launch(void* const* d_in, const int* in_sizes, int n_in,
                              void* d_out, int out_size)
{
    const float* hs = (const float*)d_in[0];
    const float* pe = (const float*)d_in[1];
    const float* Wq = (const float*)d_in[2];
    const float* Wk = (const float*)d_in[3];
    const float* Wv = (const float*)d_in[4];
    const float* Wo = (const float*)d_in[5];
    const float* Wp = (const float*)d_in[6];
    const float* bu = (const float*)d_in[7];
    const float* bv = (const float*)d_in[8];
    float* out = (float*)d_out;

    unsigned short *hshi, *hslo, *pehi, *pelo;
    unsigned short *wqh, *wql, *wkh, *wkl, *wvh, *wvl, *woh, *wol, *wph, *wpl;
    cudaGetSymbolAddress((void**)&hshi, g_hshi); cudaGetSymbolAddress((void**)&hslo, g_hslo);
    cudaGetSymbolAddress((void**)&pehi, g_pehi); cudaGetSymbolAddress((void**)&pelo, g_pelo);
    cudaGetSymbolAddress((void**)&wqh, g_Wqhi);  cudaGetSymbolAddress((void**)&wql, g_Wqlo);
    cudaGetSymbolAddress((void**)&wkh, g_Wkhi);  cudaGetSymbolAddress((void**)&wkl, g_Wklo);
    cudaGetSymbolAddress((void**)&wvh, g_Wvhi);  cudaGetSymbolAddress((void**)&wvl, g_Wvlo);
    cudaGetSymbolAddress((void**)&woh, g_Wohi);  cudaGetSymbolAddress((void**)&wol, g_Wolo);
    cudaGetSymbolAddress((void**)&wph, g_Wphi);  cudaGetSymbolAddress((void**)&wpl, g_Wplo);

    static int attr_done = 0;
    if (!attr_done) {
        cudaFuncSetAttribute(k_qkv, cudaFuncAttributeMaxDynamicSharedMemorySize, DYN_BYTES);
        cudaFuncSetAttribute(k_p,   cudaFuncAttributeMaxDynamicSharedMemorySize, DYN_BYTES);
        cudaFuncSetAttribute(k_ac,  cudaFuncAttributeMaxDynamicSharedMemorySize, DYN_BYTES);
        cudaFuncSetAttribute(k_bd,  cudaFuncAttributeMaxDynamicSharedMemorySize, DYN_BYTES);
        cudaFuncSetAttribute(k_av,  cudaFuncAttributeMaxDynamicSharedMemorySize, DYN_BYTES);
        cudaFuncSetAttribute(k_out, cudaFuncAttributeMaxDynamicSharedMemorySize, DYN_BYTES);
        attr_done = 1;
    }

    k_split<<<(MHS*DD + 255)/256, 256>>>(hs, hshi, hslo, MHS*DD);
    k_split<<<(PP*DD + 255)/256, 256>>>(pe, pehi, pelo, PP*DD);
    k_split<<<(DD*DD + 255)/256, 256>>>(Wq, wqh, wql, DD*DD);
    k_split<<<(DD*DD + 255)/256, 256>>>(Wk, wkh, wkl, DD*DD);
    k_split<<<(DD*DD + 255)/256, 256>>>(Wv, wvh, wvl, DD*DD);
    k_split<<<(DD*DD + 255)/256, 256>>>(Wo, woh, wol, DD*DD);
    k_split<<<(DD*DD + 255)/256, 256>>>(Wp, wph, wpl, DD*DD);

    k_qkv<<<dim3(8, 32, 3), 256, DYN_BYTES>>>(bu, bv);
    k_p  <<<dim3(8, 16),    256, DYN_BYTES>>>();
    k_ac <<<dim3(8, 8, BATCH*HH),  256, DYN_BYTES>>>();
    k_bd <<<dim3(16, 8, BATCH*HH), 256, DYN_BYTES>>>();
    k_softmax<<<BATCH*HH*TT, 256>>>();
    k_av <<<dim3(1, 8, BATCH*HH),  256, DYN_BYTES>>>();
    k_out<<<dim3(8, 32),    256, DYN_BYTES>>>(out);
}

// round 9
// speedup vs baseline: 1.7666x; 1.2869x over previous
#include <cuda_runtime.h>
#include <cuda_fp16.h>
#include <stdint.h>

#define BATCH 4
#define TT    1024
#define DD    1024
#define HH    8
#define DKK   128
#define PP    2047
#define MHS   (BATCH*TT)
#define BK    32
#define ROWP  40                        // padded smem row stride (halves)
#define BUFP  (128*ROWP)                // halves per buffer
#define STAGEH (3*BUFP)                 // halves per stage (Ah, Bh, Bl)
#define STAGES 3
#define DYN_BYTES (STAGES*STAGEH*2)     // 92160 B

#define PE_N (PP*DD)

// ---------------- scratch (device globals) -----------------------------------
// A-side tensors: hi only. B-side tensors: hi + lo.
__device__ __half g_hsh[MHS*DD];
__device__ __half g_peh[PE_N];
__device__ __half g_Wqh[DD*DD], g_Wql[DD*DD];
__device__ __half g_Wkh[DD*DD], g_Wkl[DD*DD];
__device__ __half g_Wvh[DD*DD], g_Wvl[DD*DD];
__device__ __half g_Woh[DD*DD], g_Wol[DD*DD];
__device__ __half g_Wph[DD*DD], g_Wpl[DD*DD];
__device__ __half g_quh[BATCH*HH*TT*DKK];                       // A-side
__device__ __half g_qvh[BATCH*HH*TT*DKK];                       // A-side
__device__ __half g_kh [BATCH*HH*TT*DKK], g_kl [BATCH*HH*TT*DKK];
__device__ __half g_vTh[BATCH*HH*DKK*TT], g_vTl[BATCH*HH*DKK*TT]; // (b,h,d,t)
__device__ __half g_ph [HH*PP*DKK],       g_pl [HH*PP*DKK];
__device__ __half g_ath[(size_t)BATCH*HH*TT*TT];                // A-side probs
__device__ __half g_oh [MHS*DD];                                // A-side
__device__ float g_scores[(size_t)BATCH*HH*TT*TT];              // 134 MB fp32

typedef const __half* hp;

// ---------------- helpers ---------------------------------------------------
__device__ __forceinline__ void split2h(float x, __half& h, __half& l)
{
    h = __float2half_rn(x);
    l = __float2half_rn(x - __half2float(h));
}

__device__ __forceinline__ uint32_t cvta_s(const void* p)
{
    uint32_t a;
    asm("{ .reg .u64 t; cvta.to.shared.u64 t, %1; cvt.u32.u64 %0, t; }" : "=r"(a) : "l"(p));
    return a;
}

#define MMA_F16(D, A, B0, B1)                                              \
    asm volatile("mma.sync.aligned.m16n8k16.row.col.f32.f16.f16.f32 "      \
                 "{%0,%1,%2,%3}, {%4,%5,%6,%7}, {%8,%9}, {%0,%1,%2,%3};"   \
                 : "+f"(D[0]), "+f"(D[1]), "+f"(D[2]), "+f"(D[3])          \
                 : "r"(A[0]), "r"(A[1]), "r"(A[2]), "r"(A[3]),             \
                   "r"(B0), "r"(B1))

#define LDSM4(R, addr)                                                          \
    asm volatile("ldmatrix.sync.aligned.m8n8.x4.shared.b16 {%0,%1,%2,%3}, [%4];"\
                 : "=r"((R)[0]), "=r"((R)[1]), "=r"((R)[2]), "=r"((R)[3])       \
                 : "r"(addr))

// ---------------- async stage loader (3 buffers: Ah, Bh, Bl) -----------------
__device__ __forceinline__ void load_stage(__half* sm, int s,
    hp Ah, int M, hp Bh, hp Bl, int N, int K, int row0, int col0, int k0)
{
    __half* st = sm + s * STAGEH;
    const int tid = threadIdx.x;
    #pragma unroll
    for (int buf = 0; buf < 3; buf++) {
        hp src = (buf == 0) ? Ah : (buf == 1) ? Bh : Bl;
        const int g0  = (buf == 0) ? row0 : col0;
        const int lim = (buf == 0) ? M    : N;
        __half* db = st + buf * BUFP;
        #pragma unroll
        for (int t = 0; t < 2; t++) {
            int slot = tid + t * 256;          // 0..511
            int r = slot >> 2, seg = slot & 3;
            int g = g0 + r;
            int ok = (g < lim);
            const __half* sp = src + (size_t)(ok ? g : 0) * K + k0 + seg * 8;
            uint32_t d = cvta_s(db + r * ROWP + seg * 8);
            asm volatile("cp.async.cg.shared.global [%0], [%1], 16, %2;"
                         :: "r"(d), "l"(sp), "r"(ok ? 16 : 0) : "memory");
        }
    }
}

// ---------------- 2-term NT mainloop: C = A(MxK) * (Bhi+Blo)(NxK)^T ----------
// 128x128 tile, 256 threads (8 warps of 32x64), BK=32, cp.async 3-stage.
__device__ __forceinline__ void hmma_main(
    hp Ah, int M, hp Bh, hp Bl, int N,
    int K, int row0, int col0, float acc[2][8][4])
{
    extern __shared__ __half smv[];
    const int tid = threadIdx.x, lane = tid & 31, warp = tid >> 5;
    const int wm = warp >> 1, wn = warp & 1;
    const int mi = lane >> 3, lr8 = lane & 7;
    const int row_off = (mi & 1) * 8 + lr8;
    const int col_off = (mi >> 1) * 8;

    const int niter = K >> 5;
    load_stage(smv, 0, Ah, M, Bh, Bl, N, K, row0, col0, 0);
    asm volatile("cp.async.commit_group;" ::: "memory");
    if (niter > 1) {
        load_stage(smv, 1, Ah, M, Bh, Bl, N, K, row0, col0, 32);
    }
    asm volatile("cp.async.commit_group;" ::: "memory");

    for (int it = 0; it < niter; it++) {
        if (it + 2 < niter) {
            load_stage(smv, (it + 2) % STAGES, Ah, M, Bh, Bl, N, K,
                       row0, col0, (it + 2) << 5);
            asm volatile("cp.async.commit_group;" ::: "memory");
            asm volatile("cp.async.wait_group 2;" ::: "memory");
        } else if (it + 1 < niter) {
            asm volatile("cp.async.wait_group 1;" ::: "memory");
        } else {
            asm volatile("cp.async.wait_group 0;" ::: "memory");
        }
        __syncthreads();

        const __half* st = smv + (it % STAGES) * STAGEH;
        #pragma unroll
        for (int kb = 0; kb < BK; kb += 16) {
            uint32_t a[2][4];
            #pragma unroll
            for (int i = 0; i < 2; i++) {
                int off = (wm * 32 + i * 16 + row_off) * ROWP + kb + col_off;
                LDSM4(a[i], cvta_s(st + off));                    // buf 0: A
            }
            #pragma unroll
            for (int g = 0; g < 4; g++) {
                uint32_t bh4[4], bl4[4];
                int off = (wn * 64 + g * 16 + row_off) * ROWP + kb + col_off;
                LDSM4(bh4, cvta_s(st + BUFP + off));              // buf 1: B hi
                LDSM4(bl4, cvta_s(st + 2 * BUFP + off));          // buf 2: B lo
                #pragma unroll
                for (int i = 0; i < 2; i++) {
                    MMA_F16(acc[i][g*2],   a[i], bh4[0], bh4[2]);
                    MMA_F16(acc[i][g*2],   a[i], bl4[0], bl4[2]);
                    MMA_F16(acc[i][g*2+1], a[i], bh4[1], bh4[3]);
                    MMA_F16(acc[i][g*2+1], a[i], bl4[1], bl4[3]);
                }
            }
        }
        __syncthreads();
    }
}

// epilogue coordinate helpers (per thread)
#define EPI_ROW(i, r)  (wm*32 + (i)*16 + grp + ((r) >> 1)*8)
#define EPI_COL(j, r)  (wn*64 + (j)*8 + qid*2 + ((r) & 1))
#define EPI_DECLS                                          \
    const int lane = threadIdx.x & 31;                     \
    const int warp = threadIdx.x >> 5;                     \
    const int grp = lane >> 2, qid = lane & 3;             \
    const int wm = warp >> 1, wn = warp & 1;

// ---------------- splits -----------------------------------------------------
__global__ void k_split_hs(const float* __restrict__ hs)
{
    int i = blockIdx.x * blockDim.x + threadIdx.x;
    if (i < MHS*DD) g_hsh[i] = __float2half_rn(hs[i]);
}

__global__ void k_split_rest(const float* __restrict__ pe,
                             const float* __restrict__ Wq,
                             const float* __restrict__ Wk,
                             const float* __restrict__ Wv,
                             const float* __restrict__ Wo,
                             const float* __restrict__ Wp)
{
    int i = blockIdx.x * blockDim.x + threadIdx.x;
    if (i < PE_N) { g_peh[i] = __float2half_rn(pe[i]); return; }
    int j = i - PE_N;
    if (j >= 5 * DD * DD) return;
    int w = j >> 20, o = j & (DD*DD - 1);
    const float* src = (w == 0) ? Wq : (w == 1) ? Wk : (w == 2) ? Wv
                     : (w == 3) ? Wo : Wp;
    __half* dh = (w == 0) ? g_Wqh : (w == 1) ? g_Wkh : (w == 2) ? g_Wvh
               : (w == 3) ? g_Woh : g_Wph;
    __half* dl = (w == 0) ? g_Wql : (w == 1) ? g_Wkl : (w == 2) ? g_Wvl
               : (w == 3) ? g_Wol : g_Wpl;
    split2h(src[o], dh[o], dl[o]);
}

// ---------------- Q/K/V projection ------------------------------------------
__global__ void __launch_bounds__(256, 2)
k_qkv(const float* __restrict__ bu, const float* __restrict__ bv)
{
    const int z = blockIdx.z;
    hp Wh = (z == 0) ? g_Wqh : (z == 1) ? g_Wkh : g_Wvh;
    hp Wl = (z == 0) ? g_Wql : (z == 1) ? g_Wkl : g_Wvl;
    const int row0 = blockIdx.y * 128, col0 = blockIdx.x * 128;
    float acc[2][8][4] = {};
    hmma_main(g_hsh, MHS, Wh, Wl, DD, DD, row0, col0, acc);
    EPI_DECLS
    #pragma unroll
    for (int i = 0; i < 2; i++)
        #pragma unroll
        for (int j = 0; j < 8; j++)
            #pragma unroll
            for (int r = 0; r < 4; r++) {
                int m = row0 + EPI_ROW(i, r);
                int n = col0 + EPI_COL(j, r);
                int b = m >> 10, t = m & 1023;
                int h = n >> 7,  d = n & 127;
                float v = acc[i][j][r];
                size_t idx = ((size_t)(b*HH + h)*TT + t)*DKK + d;
                if (z == 0) {
                    g_quh[idx] = __float2half_rn(v + bu[h*DKK + d]);
                    g_qvh[idx] = __float2half_rn(v + bv[h*DKK + d]);
                } else if (z == 1) {
                    split2h(v, g_kh[idx], g_kl[idx]);
                } else {
                    size_t it = ((size_t)(b*HH + h)*DKK + d)*TT + t;  // transposed
                    split2h(v, g_vTh[it], g_vTl[it]);
                }
            }
}

// ---------------- P projection ----------------------------------------------
__global__ void __launch_bounds__(256, 2) k_p()
{
    const int row0 = blockIdx.y * 128, col0 = blockIdx.x * 128;
    float acc[2][8][4] = {};
    hmma_main(g_peh, PP, g_Wph, g_Wpl, DD, DD, row0, col0, acc);
    EPI_DECLS
    #pragma unroll
    for (int i = 0; i < 2; i++)
        #pragma unroll
        for (int j = 0; j < 8; j++)
            #pragma unroll
            for (int r = 0; r < 4; r++) {
                int m = row0 + EPI_ROW(i, r);
                if (m >= PP) continue;
                int n = col0 + EPI_COL(j, r);
                int h = n >> 7, d = n & 127;
                size_t idx = ((size_t)h*PP + m)*DKK + d;
                split2h(acc[i][j][r], g_ph[idx], g_pl[idx]);
            }
}

// ---------------- AC: scores = qu @ k^T per (b,h) ---------------------------
__global__ void __launch_bounds__(256, 2) k_ac()
{
    const int bh = blockIdx.z;
    const size_t ob = (size_t)bh * TT * DKK;
    const int row0 = blockIdx.y * 128, col0 = blockIdx.x * 128;
    float acc[2][8][4] = {};
    hmma_main(g_quh + ob, TT, g_kh + ob, g_kl + ob, TT, DKK, row0, col0, acc);
    EPI_DECLS
    float* C = g_scores + (size_t)bh * TT * TT;
    #pragma unroll
    for (int i = 0; i < 2; i++)
        #pragma unroll
        for (int j = 0; j < 8; j++)
            #pragma unroll
            for (int r = 0; r < 4; r++) {
                int m = row0 + EPI_ROW(i, r);
                int n = col0 + EPI_COL(j, r);
                C[(size_t)m * TT + n] = acc[i][j][r];
            }
}

// ---------------- BD: scores[m, n+m-1023] += qv @ p^T (rel-shift fused) -----
__global__ void __launch_bounds__(256, 2) k_bd()
{
    const int bh = blockIdx.z, h = bh & 7;
    const int row0 = blockIdx.y * 128, col0 = blockIdx.x * 128;
    if (row0 + col0 + 254 < 1023 || row0 + col0 > 2046) return; // no k in [0,T)
    const size_t oa = (size_t)bh * TT * DKK;
    const size_t op = (size_t)h * PP * DKK;
    float acc[2][8][4] = {};
    hmma_main(g_qvh + oa, TT, g_ph + op, g_pl + op, PP, DKK, row0, col0, acc);
    EPI_DECLS
    float* C = g_scores + (size_t)bh * TT * TT;
    #pragma unroll
    for (int i = 0; i < 2; i++)
        #pragma unroll
        for (int j = 0; j < 8; j++)
            #pragma unroll
            for (int r = 0; r < 4; r++) {
                int m = row0 + EPI_ROW(i, r);
                int n = col0 + EPI_COL(j, r);
                if (n < PP) {
                    int k = n + m - 1023;
                    if ((unsigned)k < (unsigned)TT)
                        C[(size_t)m * TT + k] += acc[i][j][r];
                }
            }
}

// ---------------- softmax: fp32 scores -> attn fp16 -------------------------
__global__ void k_softmax()
{
    const size_t rowoff = (size_t)blockIdx.x * TT;
    const float* r = g_scores + rowoff;
    const int tid = threadIdx.x;                 // 256 threads, float4 each
    float4 v = reinterpret_cast<const float4*>(r)[tid];
    const float s = 0.08838834764831845f;        // 1/sqrt(128)
    v.x *= s; v.y *= s; v.z *= s; v.w *= s;

    __shared__ float redm[8];
    __shared__ float reds[8];

    float m = fmaxf(fmaxf(v.x, v.y), fmaxf(v.z, v.w));
    #pragma unroll
    for (int o = 16; o > 0; o >>= 1) m = fmaxf(m, __shfl_xor_sync(~0u, m, o));
    if ((tid & 31) == 0) redm[tid >> 5] = m;
    __syncthreads();
    m = redm[0];
    #pragma unroll
    for (int w = 1; w < 8; w++) m = fmaxf(m, redm[w]);

    float4 e;
    e.x = __expf(v.x - m); e.y = __expf(v.y - m);
    e.z = __expf(v.z - m); e.w = __expf(v.w - m);
    float sum = e.x + e.y + e.z + e.w;
    #pragma unroll
    for (int o = 16; o > 0; o >>= 1) sum += __shfl_xor_sync(~0u, sum, o);
    if ((tid & 31) == 0) reds[tid >> 5] = sum;
    __syncthreads();
    sum = reds[0];
    #pragma unroll
    for (int w = 1; w < 8; w++) sum += reds[w];

    float inv = __frcp_rn(sum);
    __half2 p01 = __floats2half2_rn(e.x * inv, e.y * inv);
    __half2 p23 = __floats2half2_rn(e.z * inv, e.w * inv);
    size_t base = rowoff + (size_t)tid * 4;
    uint2 pk;
    pk.x = *reinterpret_cast<uint32_t*>(&p01);
    pk.y = *reinterpret_cast<uint32_t*>(&p23);
    *reinterpret_cast<uint2*>(&g_ath[base]) = pk;
}

// ---------------- AV: o = attn @ v per (b,h) (B = vT, NT form) --------------
__global__ void __launch_bounds__(256, 2) k_av()
{
    const int bh = blockIdx.z, b = bh >> 3, h = bh & 7;
    const size_t oa = (size_t)bh * TT * TT;
    const size_t ov = (size_t)bh * DKK * TT;
    const int row0 = blockIdx.y * 128;
    float acc[2][8][4] = {};
    hmma_main(g_ath + oa, TT, g_vTh + ov, g_vTl + ov, DKK, TT, row0, 0, acc);
    EPI_DECLS
    #pragma unroll
    for (int i = 0; i < 2; i++)
        #pragma unroll
        for (int j = 0; j < 8; j++)
            #pragma unroll
            for (int r = 0; r < 4; r++) {
                int m = row0 + EPI_ROW(i, r);
                int n = EPI_COL(j, r);              // head-dim 0..127
                size_t idx = ((size_t)(b*TT + m)*HH + h)*DKK + n; // (b,t,h,d)
                g_oh[idx] = __float2half_rn(acc[i][j][r]);
            }
}

// ---------------- output projection -----------------------------------------
__global__ void __launch_bounds__(256, 2) k_out(float* __restrict__ out)
{
    const int row0 = blockIdx.y * 128, col0 = blockIdx.x * 128;
    float acc[2][8][4] = {};
    hmma_main(g_oh, MHS, g_Woh, g_Wol, DD, DD, row0, col0, acc);
    EPI_DECLS
    #pragma unroll
    for (int i = 0; i < 2; i++)
        #pragma unroll
        for (int j = 0; j < 8; j++)
            #pragma unroll
            for (int r = 0; r < 4; r++) {
                int m = row0 + EPI_ROW(i, r);
                int n = col0 + EPI_COL(j, r);
                out[(size_t)m * DD + n] = acc[i][j][r];
            }
}

// ---------------- launch ----------------------------------------------------
extern "C" void kernel_launch(void* const* d_in, const int* in_sizes, int n_in,
                              void* d_out, int out_size)
{
    const float* hs = (const float*)d_in[0];
    const float* pe = (const float*)d_in[1];
    const float* Wq = (const float*)d_in[2];
    const float* Wk = (const float*)d_in[3];
    const float* Wv = (const float*)d_in[4];
    const float* Wo = (const float*)d_in[5];
    const float* Wp = (const float*)d_in[6];
    const float* bu = (const float*)d_in[7];
    const float* bv = (const float*)d_in[8];
    float* out = (float*)d_out;

    static int attr_done = 0;
    if (!attr_done) {
        cudaFuncSetAttribute(k_qkv, cudaFuncAttributeMaxDynamicSharedMemorySize, DYN_BYTES);
        cudaFuncSetAttribute(k_p,   cudaFuncAttributeMaxDynamicSharedMemorySize, DYN_BYTES);
        cudaFuncSetAttribute(k_ac,  cudaFuncAttributeMaxDynamicSharedMemorySize, DYN_BYTES);
        cudaFuncSetAttribute(k_bd,  cudaFuncAttributeMaxDynamicSharedMemorySize, DYN_BYTES);
        cudaFuncSetAttribute(k_av,  cudaFuncAttributeMaxDynamicSharedMemorySize, DYN_BYTES);
        cudaFuncSetAttribute(k_out, cudaFuncAttributeMaxDynamicSharedMemorySize, DYN_BYTES);
        attr_done = 1;
    }

    // launch order keeps k_bd at position 6 so ncu (-s 5 -c 1) profiles it
    k_split_hs  <<<(MHS*DD + 255)/256, 256>>>(hs);
    k_split_rest<<<(PE_N + 5*DD*DD + 255)/256, 256>>>(pe, Wq, Wk, Wv, Wo, Wp);

    k_qkv<<<dim3(8, 32, 3), 256, DYN_BYTES>>>(bu, bv);
    k_p  <<<dim3(8, 16),    256, DYN_BYTES>>>();
    k_ac <<<dim3(8, 8, BATCH*HH),  256, DYN_BYTES>>>();
    k_bd <<<dim3(16, 8, BATCH*HH), 256, DYN_BYTES>>>();
    k_softmax<<<BATCH*HH*TT, 256>>>();
    k_av <<<dim3(1, 8, BATCH*HH),  256, DYN_BYTES>>>();
    k_out<<<dim3(8, 32),    256, DYN_BYTES>>>(out);
}

// round 10
// speedup vs baseline: 1.9633x; 1.1113x over previous
#include <cuda_runtime.h>
#include <cuda_fp16.h>
#include <stdint.h>

#define BATCH 4
#define TT    1024
#define DD    1024
#define HH    8
#define DKK   128
#define PP    2047
#define MHS   (BATCH*TT)
#define BK    32
#define ROWP  40                        // padded smem row stride (halves)
#define BUFP  (128*ROWP)                // halves per buffer
#define STAGES 3
#define DYN3  (STAGES*3*BUFP*2)         // 92160 B (two-term: A, Bhi, Blo)
#define DYN2  (STAGES*2*BUFP*2)         // 61440 B (one-term: A, Bhi)
#define PE_N  (PP*DD)

// ---------------- scratch (device globals) -----------------------------------
__device__ __half g_hsh[MHS*DD];
__device__ __half g_peh[PE_N];
__device__ __half g_Wqh[DD*DD], g_Wql[DD*DD];
__device__ __half g_Wkh[DD*DD], g_Wkl[DD*DD];
__device__ __half g_Wvh[DD*DD];                     // one-term
__device__ __half g_Woh[DD*DD];                     // one-term
__device__ __half g_Wph[DD*DD], g_Wpl[DD*DD];
__device__ __half g_quh[BATCH*HH*TT*DKK];           // A-side
__device__ __half g_qvh[BATCH*HH*TT*DKK];           // A-side
__device__ __half g_kh [BATCH*HH*TT*DKK], g_kl [BATCH*HH*TT*DKK];
__device__ __half g_vTh[BATCH*HH*DKK*TT];           // (b,h,d,t) one-term
__device__ __half g_ph [HH*PP*DKK],       g_pl [HH*PP*DKK];
__device__ __half g_ath[(size_t)BATCH*HH*TT*TT];    // A-side probs
__device__ __half g_oh [MHS*DD];                    // A-side
__device__ float g_scores[(size_t)BATCH*HH*TT*TT];  // 134 MB fp32

typedef const __half* hp;

// ---------------- helpers ---------------------------------------------------
__device__ __forceinline__ void split2h(float x, __half& h, __half& l)
{
    h = __float2half_rn(x);
    l = __float2half_rn(x - __half2float(h));
}

__device__ __forceinline__ uint32_t cvta_s(const void* p)
{
    uint32_t a;
    asm("{ .reg .u64 t; cvta.to.shared.u64 t, %1; cvt.u32.u64 %0, t; }" : "=r"(a) : "l"(p));
    return a;
}

#define MMA_F16(D, A, B0, B1)                                              \
    asm volatile("mma.sync.aligned.m16n8k16.row.col.f32.f16.f16.f32 "      \
                 "{%0,%1,%2,%3}, {%4,%5,%6,%7}, {%8,%9}, {%0,%1,%2,%3};"   \
                 : "+f"(D[0]), "+f"(D[1]), "+f"(D[2]), "+f"(D[3])          \
                 : "r"(A[0]), "r"(A[1]), "r"(A[2]), "r"(A[3]),             \
                   "r"(B0), "r"(B1))

#define LDSM4(R, addr)                                                          \
    asm volatile("ldmatrix.sync.aligned.m8n8.x4.shared.b16 {%0,%1,%2,%3}, [%4];"\
                 : "=r"((R)[0]), "=r"((R)[1]), "=r"((R)[2]), "=r"((R)[3])       \
                 : "r"(addr))

// ---------------- async stage loader ----------------------------------------
template<int NBUF>
__device__ __forceinline__ void load_stage(__half* sm, int s,
    hp Ah, int M, hp Bh, hp Bl, int N, int K, int row0, int col0, int k0)
{
    __half* st = sm + s * (NBUF * BUFP);
    const int tid = threadIdx.x;
    #pragma unroll
    for (int buf = 0; buf < NBUF; buf++) {
        hp src = (buf == 0) ? Ah : (buf == 1) ? Bh : Bl;
        const int g0  = (buf == 0) ? row0 : col0;
        const int lim = (buf == 0) ? M    : N;
        __half* db = st + buf * BUFP;
        #pragma unroll
        for (int t = 0; t < 2; t++) {
            int slot = tid + t * 256;          // 0..511
            int r = slot >> 2, seg = slot & 3;
            int g = g0 + r;
            int ok = (g < lim);
            const __half* sp = src + (size_t)(ok ? g : 0) * K + k0 + seg * 8;
            uint32_t d = cvta_s(db + r * ROWP + seg * 8);
            asm volatile("cp.async.cg.shared.global [%0], [%1], 16, %2;"
                         :: "r"(d), "l"(sp), "r"(ok ? 16 : 0) : "memory");
        }
    }
}

// ---------------- NT mainloop: C = A(MxK) * (Bhi[+Blo])(NxK)^T ---------------
// 128x128 tile, 256 threads (8 warps of 32x64), BK=32, cp.async 3-stage.
template<int NBUF>
__device__ __forceinline__ void hmma_main(
    hp Ah, int M, hp Bh, hp Bl, int N,
    int K, int row0, int col0, float acc[2][8][4])
{
    extern __shared__ __half smv[];
    const int stageh = NBUF * BUFP;
    const int tid = threadIdx.x, lane = tid & 31, warp = tid >> 5;
    const int wm = warp >> 1, wn = warp & 1;
    const int mi = lane >> 3, lr8 = lane & 7;
    const int row_off = (mi & 1) * 8 + lr8;
    const int col_off = (mi >> 1) * 8;

    const int niter = K >> 5;
    load_stage<NBUF>(smv, 0, Ah, M, Bh, Bl, N, K, row0, col0, 0);
    asm volatile("cp.async.commit_group;" ::: "memory");
    if (niter > 1) {
        load_stage<NBUF>(smv, 1, Ah, M, Bh, Bl, N, K, row0, col0, 32);
    }
    asm volatile("cp.async.commit_group;" ::: "memory");

    for (int it = 0; it < niter; it++) {
        if (it + 2 < niter) {
            load_stage<NBUF>(smv, (it + 2) % STAGES, Ah, M, Bh, Bl, N, K,
                             row0, col0, (it + 2) << 5);
            asm volatile("cp.async.commit_group;" ::: "memory");
            asm volatile("cp.async.wait_group 2;" ::: "memory");
        } else if (it + 1 < niter) {
            asm volatile("cp.async.wait_group 1;" ::: "memory");
        } else {
            asm volatile("cp.async.wait_group 0;" ::: "memory");
        }
        __syncthreads();

        const __half* st = smv + (it % STAGES) * stageh;
        #pragma unroll
        for (int kb = 0; kb < BK; kb += 16) {
            uint32_t a[2][4];
            #pragma unroll
            for (int i = 0; i < 2; i++) {
                int off = (wm * 32 + i * 16 + row_off) * ROWP + kb + col_off;
                LDSM4(a[i], cvta_s(st + off));                    // buf 0: A
            }
            #pragma unroll
            for (int g = 0; g < 4; g++) {
                int off = (wn * 64 + g * 16 + row_off) * ROWP + kb + col_off;
                uint32_t bh4[4];
                LDSM4(bh4, cvta_s(st + BUFP + off));              // buf 1: B hi
                if (NBUF == 3) {
                    uint32_t bl4[4];
                    LDSM4(bl4, cvta_s(st + 2 * BUFP + off));      // buf 2: B lo
                    // 4 independent accs between same-acc reuse
                    MMA_F16(acc[0][g*2],   a[0], bh4[0], bh4[2]);
                    MMA_F16(acc[1][g*2],   a[1], bh4[0], bh4[2]);
                    MMA_F16(acc[0][g*2+1], a[0], bh4[1], bh4[3]);
                    MMA_F16(acc[1][g*2+1], a[1], bh4[1], bh4[3]);
                    MMA_F16(acc[0][g*2],   a[0], bl4[0], bl4[2]);
                    MMA_F16(acc[1][g*2],   a[1], bl4[0], bl4[2]);
                    MMA_F16(acc[0][g*2+1], a[0], bl4[1], bl4[3]);
                    MMA_F16(acc[1][g*2+1], a[1], bl4[1], bl4[3]);
                } else {
                    MMA_F16(acc[0][g*2],   a[0], bh4[0], bh4[2]);
                    MMA_F16(acc[1][g*2],   a[1], bh4[0], bh4[2]);
                    MMA_F16(acc[0][g*2+1], a[0], bh4[1], bh4[3]);
                    MMA_F16(acc[1][g*2+1], a[1], bh4[1], bh4[3]);
                }
            }
        }
        __syncthreads();
    }
}

// epilogue coordinate helpers (per thread)
#define EPI_ROW(i, r)  (wm*32 + (i)*16 + grp + ((r) >> 1)*8)
#define EPI_COL(j, r)  (wn*64 + (j)*8 + qid*2 + ((r) & 1))
#define EPI_DECLS                                          \
    const int lane = threadIdx.x & 31;                     \
    const int warp = threadIdx.x >> 5;                     \
    const int grp = lane >> 2, qid = lane & 3;             \
    const int wm = warp >> 1, wn = warp & 1;

// ---------------- splits -----------------------------------------------------
__global__ void k_split_hs(const float* __restrict__ hs)
{
    int i = blockIdx.x * blockDim.x + threadIdx.x;
    if (i < MHS*DD) g_hsh[i] = __float2half_rn(hs[i]);
}

__global__ void k_split_rest(const float* __restrict__ pe,
                             const float* __restrict__ Wq,
                             const float* __restrict__ Wk,
                             const float* __restrict__ Wv,
                             const float* __restrict__ Wo,
                             const float* __restrict__ Wp)
{
    int i = blockIdx.x * blockDim.x + threadIdx.x;
    if (i < PE_N) { g_peh[i] = __float2half_rn(pe[i]); return; }
    int j = i - PE_N;
    if (j >= 5 * DD * DD) return;
    int w = j >> 20, o = j & (DD*DD - 1);
    const float* src = (w == 0) ? Wq : (w == 1) ? Wk : (w == 2) ? Wv
                     : (w == 3) ? Wo : Wp;
    if (w == 2)      { g_Wvh[o] = __float2half_rn(src[o]); }
    else if (w == 3) { g_Woh[o] = __float2half_rn(src[o]); }
    else {
        __half* dh = (w == 0) ? g_Wqh : (w == 1) ? g_Wkh : g_Wph;
        __half* dl = (w == 0) ? g_Wql : (w == 1) ? g_Wkl : g_Wpl;
        split2h(src[o], dh[o], dl[o]);
    }
}

// ---------------- Q / K / P projections (two-term), merged launch ------------
__global__ void __launch_bounds__(256, 2)
k_projQKP(const float* __restrict__ bu, const float* __restrict__ bv)
{
    const int z = blockIdx.z;                     // 0:Q  1:K  2:P
    if (z == 2 && blockIdx.y >= 16) return;       // P has 16 row tiles
    hp Ah = (z == 2) ? g_peh : g_hsh;
    const int M = (z == 2) ? PP : MHS;
    hp Wh = (z == 0) ? g_Wqh : (z == 1) ? g_Wkh : g_Wph;
    hp Wl = (z == 0) ? g_Wql : (z == 1) ? g_Wkl : g_Wpl;
    const int row0 = blockIdx.y * 128, col0 = blockIdx.x * 128;
    float acc[2][8][4] = {};
    hmma_main<3>(Ah, M, Wh, Wl, DD, DD, row0, col0, acc);
    EPI_DECLS
    #pragma unroll
    for (int i = 0; i < 2; i++)
        #pragma unroll
        for (int j = 0; j < 8; j++)
            #pragma unroll
            for (int r = 0; r < 4; r++) {
                int m = row0 + EPI_ROW(i, r);
                int n = col0 + EPI_COL(j, r);
                int h = n >> 7, d = n & 127;
                float v = acc[i][j][r];
                if (z == 0) {
                    int b = m >> 10, t = m & 1023;
                    size_t idx = ((size_t)(b*HH + h)*TT + t)*DKK + d;
                    g_quh[idx] = __float2half_rn(v + bu[h*DKK + d]);
                    g_qvh[idx] = __float2half_rn(v + bv[h*DKK + d]);
                } else if (z == 1) {
                    int b = m >> 10, t = m & 1023;
                    size_t idx = ((size_t)(b*HH + h)*TT + t)*DKK + d;
                    split2h(v, g_kh[idx], g_kl[idx]);
                } else {
                    if (m < PP) {
                        size_t idx = ((size_t)h*PP + m)*DKK + d;
                        split2h(v, g_ph[idx], g_pl[idx]);
                    }
                }
            }
}

// ---------------- V projection (one-term), transposed store ------------------
__global__ void __launch_bounds__(256, 2) k_projV()
{
    const int row0 = blockIdx.y * 128, col0 = blockIdx.x * 128;
    float acc[2][8][4] = {};
    hmma_main<2>(g_hsh, MHS, g_Wvh, (hp)0, DD, DD, row0, col0, acc);
    EPI_DECLS
    #pragma unroll
    for (int i = 0; i < 2; i++)
        #pragma unroll
        for (int j = 0; j < 8; j++)
            #pragma unroll
            for (int r = 0; r < 4; r++) {
                int m = row0 + EPI_ROW(i, r);
                int n = col0 + EPI_COL(j, r);
                int b = m >> 10, t = m & 1023;
                int h = n >> 7,  d = n & 127;
                size_t it = ((size_t)(b*HH + h)*DKK + d)*TT + t;  // (b,h,d,t)
                g_vTh[it] = __float2half_rn(acc[i][j][r]);
            }
}

// ---------------- AC: scores = qu @ k^T per (b,h) ---------------------------
__global__ void __launch_bounds__(256, 2) k_ac()
{
    const int bh = blockIdx.z;
    const size_t ob = (size_t)bh * TT * DKK;
    const int row0 = blockIdx.y * 128, col0 = blockIdx.x * 128;
    float acc[2][8][4] = {};
    hmma_main<3>(g_quh + ob, TT, g_kh + ob, g_kl + ob, TT, DKK, row0, col0, acc);
    EPI_DECLS
    float* C = g_scores + (size_t)bh * TT * TT;
    #pragma unroll
    for (int i = 0; i < 2; i++)
        #pragma unroll
        for (int j = 0; j < 8; j++)
            #pragma unroll
            for (int r = 0; r < 4; r++) {
                int m = row0 + EPI_ROW(i, r);
                int n = col0 + EPI_COL(j, r);
                C[(size_t)m * TT + n] = acc[i][j][r];
            }
}

// ---------------- BD: scores[m, n+m-1023] += qv @ p^T (rel-shift fused) -----
// exact diagonal band: col tile index cx = bx + 7 - my  (cx+my in [7,15])
__global__ void __launch_bounds__(256, 2) k_bd()
{
    const int bh = blockIdx.z, h = bh & 7;
    const int my = blockIdx.y;
    const int cx = blockIdx.x + 7 - my;
    const int row0 = my * 128, col0 = cx * 128;
    const size_t oa = (size_t)bh * TT * DKK;
    const size_t op = (size_t)h * PP * DKK;
    float acc[2][8][4] = {};
    hmma_main<3>(g_qvh + oa, TT, g_ph + op, g_pl + op, PP, DKK, row0, col0, acc);
    EPI_DECLS
    float* C = g_scores + (size_t)bh * TT * TT;
    #pragma unroll
    for (int i = 0; i < 2; i++)
        #pragma unroll
        for (int j = 0; j < 8; j++)
            #pragma unroll
            for (int r = 0; r < 4; r++) {
                int m = row0 + EPI_ROW(i, r);
                int n = col0 + EPI_COL(j, r);
                if (n < PP) {
                    int k = n + m - 1023;
                    if ((unsigned)k < (unsigned)TT)
                        C[(size_t)m * TT + k] += acc[i][j][r];
                }
            }
}

// ---------------- softmax: fp32 scores -> attn fp16 -------------------------
__global__ void k_softmax()
{
    const size_t rowoff = (size_t)blockIdx.x * TT;
    const float* r = g_scores + rowoff;
    const int tid = threadIdx.x;                 // 256 threads, float4 each
    float4 v = reinterpret_cast<const float4*>(r)[tid];
    const float s = 0.08838834764831845f;        // 1/sqrt(128)
    v.x *= s; v.y *= s; v.z *= s; v.w *= s;

    __shared__ float redm[8];
    __shared__ float reds[8];

    float m = fmaxf(fmaxf(v.x, v.y), fmaxf(v.z, v.w));
    #pragma unroll
    for (int o = 16; o > 0; o >>= 1) m = fmaxf(m, __shfl_xor_sync(~0u, m, o));
    if ((tid & 31) == 0) redm[tid >> 5] = m;
    __syncthreads();
    m = redm[0];
    #pragma unroll
    for (int w = 1; w < 8; w++) m = fmaxf(m, redm[w]);

    float4 e;
    e.x = __expf(v.x - m); e.y = __expf(v.y - m);
    e.z = __expf(v.z - m); e.w = __expf(v.w - m);
    float sum = e.x + e.y + e.z + e.w;
    #pragma unroll
    for (int o = 16; o > 0; o >>= 1) sum += __shfl_xor_sync(~0u, sum, o);
    if ((tid & 31) == 0) reds[tid >> 5] = sum;
    __syncthreads();
    sum = reds[0];
    #pragma unroll
    for (int w = 1; w < 8; w++) sum += reds[w];

    float inv = __frcp_rn(sum);
    __half2 p01 = __floats2half2_rn(e.x * inv, e.y * inv);
    __half2 p23 = __floats2half2_rn(e.z * inv, e.w * inv);
    size_t base = rowoff + (size_t)tid * 4;
    uint2 pk;
    pk.x = *reinterpret_cast<uint32_t*>(&p01);
    pk.y = *reinterpret_cast<uint32_t*>(&p23);
    *reinterpret_cast<uint2*>(&g_ath[base]) = pk;
}

// ---------------- AV: o = attn @ v per (b,h)  (one-term) --------------------
__global__ void __launch_bounds__(256, 2) k_av()
{
    const int bh = blockIdx.z, b = bh >> 3, h = bh & 7;
    const size_t oa = (size_t)bh * TT * TT;
    const size_t ov = (size_t)bh * DKK * TT;
    const int row0 = blockIdx.y * 128;
    float acc[2][8][4] = {};
    hmma_main<2>(g_ath + oa, TT, g_vTh + ov, (hp)0, DKK, TT, row0, 0, acc);
    EPI_DECLS
    #pragma unroll
    for (int i = 0; i < 2; i++)
        #pragma unroll
        for (int j = 0; j < 8; j++)
            #pragma unroll
            for (int r = 0; r < 4; r++) {
                int m = row0 + EPI_ROW(i, r);
                int n = EPI_COL(j, r);              // head-dim 0..127
                size_t idx = ((size_t)(b*TT + m)*HH + h)*DKK + n; // (b,t,h,d)
                g_oh[idx] = __float2half_rn(acc[i][j][r]);
            }
}

// ---------------- output projection (one-term) -------------------------------
__global__ void __launch_bounds__(256, 2) k_out(float* __restrict__ out)
{
    const int row0 = blockIdx.y * 128, col0 = blockIdx.x * 128;
    float acc[2][8][4] = {};
    hmma_main<2>(g_oh, MHS, g_Woh, (hp)0, DD, DD, row0, col0, acc);
    EPI_DECLS
    #pragma unroll
    for (int i = 0; i < 2; i++)
        #pragma unroll
        for (int j = 0; j < 8; j++)
            #pragma unroll
            for (int r = 0; r < 4; r++) {
                int m = row0 + EPI_ROW(i, r);
                int n = col0 + EPI_COL(j, r);
                out[(size_t)m * DD + n] = acc[i][j][r];
            }
}

// ---------------- launch ----------------------------------------------------
extern "C" void kernel_launch(void* const* d_in, const int* in_sizes, int n_in,
                              void* d_out, int out_size)
{
    const float* hs = (const float*)d_in[0];
    const float* pe = (const float*)d_in[1];
    const float* Wq = (const float*)d_in[2];
    const float* Wk = (const float*)d_in[3];
    const float* Wv = (const float*)d_in[4];
    const float* Wo = (const float*)d_in[5];
    const float* Wp = (const float*)d_in[6];
    const float* bu = (const float*)d_in[7];
    const float* bv = (const float*)d_in[8];
    float* out = (float*)d_out;

    static int attr_done = 0;
    if (!attr_done) {
        cudaFuncSetAttribute(k_projQKP, cudaFuncAttributeMaxDynamicSharedMemorySize, DYN3);
        cudaFuncSetAttribute(k_projV,   cudaFuncAttributeMaxDynamicSharedMemorySize, DYN2);
        cudaFuncSetAttribute(k_ac,      cudaFuncAttributeMaxDynamicSharedMemorySize, DYN3);
        cudaFuncSetAttribute(k_bd,      cudaFuncAttributeMaxDynamicSharedMemorySize, DYN3);
        cudaFuncSetAttribute(k_av,      cudaFuncAttributeMaxDynamicSharedMemorySize, DYN2);
        cudaFuncSetAttribute(k_out,     cudaFuncAttributeMaxDynamicSharedMemorySize, DYN2);
        attr_done = 1;
    }

    // launch order keeps k_bd at position 6 so ncu (-s 5 -c 1) profiles it
    k_split_hs  <<<(MHS*DD + 255)/256, 256>>>(hs);
    k_split_rest<<<(PE_N + 5*DD*DD + 255)/256, 256>>>(pe, Wq, Wk, Wv, Wo, Wp);

    k_projQKP<<<dim3(8, 32, 3), 256, DYN3>>>(bu, bv);
    k_projV  <<<dim3(8, 32),    256, DYN2>>>();
    k_ac <<<dim3(8, 8, BATCH*HH), 256, DYN3>>>();
    k_bd <<<dim3(9, 8, BATCH*HH), 256, DYN3>>>();
    k_softmax<<<BATCH*HH*TT, 256>>>();
    k_av <<<dim3(1, 8, BATCH*HH), 256, DYN2>>>();
    k_out<<<dim3(8, 32),    256, DYN2>>>(out);
}

// round 11
// speedup vs baseline: 1.9977x; 1.0176x over previous
#include <cuda_runtime.h>
#include <cuda_fp16.h>
#include <stdint.h>

#define BATCH 4
#define TT    1024
#define DD    1024
#define HH    8
#define DKK   128
#define PP    2047
#define MHS   (BATCH*TT)
#define BK    32
#define ROWP  40                        // padded smem row stride (halves)
#define BUFP  (128*ROWP)                // halves per buffer
#define STAGES 3
#define DYN3  (STAGES*3*BUFP*2)         // 92160 B (two-term: A, Bhi, Blo)
#define DYN2  (STAGES*2*BUFP*2)         // 61440 B (one-term: A, Bhi)
#define PE_N  (PP*DD)

// ---------------- scratch (device globals) -----------------------------------
__device__ __half g_hsh[MHS*DD];
__device__ __half g_peh[PE_N];
__device__ __half g_Wqh[DD*DD], g_Wql[DD*DD];
__device__ __half g_Wkh[DD*DD], g_Wkl[DD*DD];
__device__ __half g_Wvh[DD*DD];                     // one-term
__device__ __half g_Woh[DD*DD];                     // one-term
__device__ __half g_Wph[DD*DD], g_Wpl[DD*DD];
__device__ __half g_quh[BATCH*HH*TT*DKK];           // A-side
__device__ __half g_qvh[BATCH*HH*TT*DKK];           // A-side
__device__ __half g_kh [BATCH*HH*TT*DKK], g_kl [BATCH*HH*TT*DKK];
__device__ __half g_vTh[BATCH*HH*DKK*TT];           // (b,h,d,t) one-term
__device__ __half g_ph [HH*PP*DKK],       g_pl [HH*PP*DKK];
__device__ __half g_ath[(size_t)BATCH*HH*TT*TT];    // A-side probs
__device__ __half g_oh [MHS*DD];                    // A-side
__device__ float g_scores[(size_t)BATCH*HH*TT*TT];  // 134 MB fp32

typedef const __half* hp;

// ---------------- helpers ---------------------------------------------------
__device__ __forceinline__ void split2h(float x, __half& h, __half& l)
{
    h = __float2half_rn(x);
    l = __float2half_rn(x - __half2float(h));
}

__device__ __forceinline__ uint32_t cvta_s(const void* p)
{
    uint32_t a;
    asm("{ .reg .u64 t; cvta.to.shared.u64 t, %1; cvt.u32.u64 %0, t; }" : "=r"(a) : "l"(p));
    return a;
}

#define MMA_F16(D, A, B0, B1)                                              \
    asm volatile("mma.sync.aligned.m16n8k16.row.col.f32.f16.f16.f32 "      \
                 "{%0,%1,%2,%3}, {%4,%5,%6,%7}, {%8,%9}, {%0,%1,%2,%3};"   \
                 : "+f"(D[0]), "+f"(D[1]), "+f"(D[2]), "+f"(D[3])          \
                 : "r"(A[0]), "r"(A[1]), "r"(A[2]), "r"(A[3]),             \
                   "r"(B0), "r"(B1))

#define LDSM4(R, addr)                                                          \
    asm volatile("ldmatrix.sync.aligned.m8n8.x4.shared.b16 {%0,%1,%2,%3}, [%4];"\
                 : "=r"((R)[0]), "=r"((R)[1]), "=r"((R)[2]), "=r"((R)[3])       \
                 : "r"(addr))

// ---------------- async stage loader ----------------------------------------
template<int NBUF>
__device__ __forceinline__ void load_stage(__half* sm, int s,
    hp Ah, int M, hp Bh, hp Bl, int N, int K, int row0, int col0, int k0)
{
    __half* st = sm + s * (NBUF * BUFP);
    const int tid = threadIdx.x;
    #pragma unroll
    for (int buf = 0; buf < NBUF; buf++) {
        hp src = (buf == 0) ? Ah : (buf == 1) ? Bh : Bl;
        const int g0  = (buf == 0) ? row0 : col0;
        const int lim = (buf == 0) ? M    : N;
        __half* db = st + buf * BUFP;
        #pragma unroll
        for (int t = 0; t < 2; t++) {
            int slot = tid + t * 256;          // 0..511
            int r = slot >> 2, seg = slot & 3;
            int g = g0 + r;
            int ok = (g < lim);
            const __half* sp = src + (size_t)(ok ? g : 0) * K + k0 + seg * 8;
            uint32_t d = cvta_s(db + r * ROWP + seg * 8);
            asm volatile("cp.async.cg.shared.global [%0], [%1], 16, %2;"
                         :: "r"(d), "l"(sp), "r"(ok ? 16 : 0) : "memory");
        }
    }
}

// ---------------- NT mainloop: C = A(MxK) * (Bhi[+Blo])(NxK)^T ---------------
// 128x128 tile, 256 threads (8 warps of 32x64), BK=32, cp.async 3-stage.
// Per k16: batch all LDSMs, then 16 independent-acc MMAs per term.
template<int NBUF>
__device__ __forceinline__ void hmma_main(
    hp Ah, int M, hp Bh, hp Bl, int N,
    int K, int row0, int col0, float acc[2][8][4])
{
    extern __shared__ __half smv[];
    const int stageh = NBUF * BUFP;
    const int tid = threadIdx.x, lane = tid & 31, warp = tid >> 5;
    const int wm = warp >> 1, wn = warp & 1;
    const int mi = lane >> 3, lr8 = lane & 7;
    const int row_off = (mi & 1) * 8 + lr8;
    const int col_off = (mi >> 1) * 8;

    const int niter = K >> 5;
    load_stage<NBUF>(smv, 0, Ah, M, Bh, Bl, N, K, row0, col0, 0);
    asm volatile("cp.async.commit_group;" ::: "memory");
    if (niter > 1) {
        load_stage<NBUF>(smv, 1, Ah, M, Bh, Bl, N, K, row0, col0, 32);
    }
    asm volatile("cp.async.commit_group;" ::: "memory");

    for (int it = 0; it < niter; it++) {
        if (it + 2 < niter) {
            load_stage<NBUF>(smv, (it + 2) % STAGES, Ah, M, Bh, Bl, N, K,
                             row0, col0, (it + 2) << 5);
            asm volatile("cp.async.commit_group;" ::: "memory");
            asm volatile("cp.async.wait_group 2;" ::: "memory");
        } else if (it + 1 < niter) {
            asm volatile("cp.async.wait_group 1;" ::: "memory");
        } else {
            asm volatile("cp.async.wait_group 0;" ::: "memory");
        }
        __syncthreads();

        const __half* st = smv + (it % STAGES) * stageh;
        #pragma unroll
        for (int kb = 0; kb < BK; kb += 16) {
            // batch-load A fragments (2) and B-hi fragments (4)
            uint32_t a[2][4];
            #pragma unroll
            for (int i = 0; i < 2; i++) {
                int off = (wm * 32 + i * 16 + row_off) * ROWP + kb + col_off;
                LDSM4(a[i], cvta_s(st + off));
            }
            uint32_t b4[4][4];
            #pragma unroll
            for (int g = 0; g < 4; g++) {
                int off = (wn * 64 + g * 16 + row_off) * ROWP + kb + col_off;
                LDSM4(b4[g], cvta_s(st + BUFP + off));
            }
            // 16 MMAs, all on distinct accumulators
            #pragma unroll
            for (int g = 0; g < 4; g++) {
                MMA_F16(acc[0][g*2],   a[0], b4[g][0], b4[g][2]);
                MMA_F16(acc[1][g*2],   a[1], b4[g][0], b4[g][2]);
                MMA_F16(acc[0][g*2+1], a[0], b4[g][1], b4[g][3]);
                MMA_F16(acc[1][g*2+1], a[1], b4[g][1], b4[g][3]);
            }
            if (NBUF == 3) {
                // reload same regs with B-lo, 16 more independent MMAs
                #pragma unroll
                for (int g = 0; g < 4; g++) {
                    int off = (wn * 64 + g * 16 + row_off) * ROWP + kb + col_off;
                    LDSM4(b4[g], cvta_s(st + 2 * BUFP + off));
                }
                #pragma unroll
                for (int g = 0; g < 4; g++) {
                    MMA_F16(acc[0][g*2],   a[0], b4[g][0], b4[g][2]);
                    MMA_F16(acc[1][g*2],   a[1], b4[g][0], b4[g][2]);
                    MMA_F16(acc[0][g*2+1], a[0], b4[g][1], b4[g][3]);
                    MMA_F16(acc[1][g*2+1], a[1], b4[g][1], b4[g][3]);
                }
            }
        }
        __syncthreads();
    }
}

// epilogue coordinate helpers (per thread)
#define EPI_ROW(i, r)  (wm*32 + (i)*16 + grp + ((r) >> 1)*8)
#define EPI_COL(j, r)  (wn*64 + (j)*8 + qid*2 + ((r) & 1))
#define EPI_DECLS                                          \
    const int lane = threadIdx.x & 31;                     \
    const int warp = threadIdx.x >> 5;                     \
    const int grp = lane >> 2, qid = lane & 3;             \
    const int wm = warp >> 1, wn = warp & 1;

// ---------------- splits -----------------------------------------------------
__global__ void k_split_hs(const float* __restrict__ hs)
{
    int i = blockIdx.x * blockDim.x + threadIdx.x;
    if (i < MHS*DD) g_hsh[i] = __float2half_rn(hs[i]);
}

__global__ void k_split_rest(const float* __restrict__ pe,
                             const float* __restrict__ Wq,
                             const float* __restrict__ Wk,
                             const float* __restrict__ Wv,
                             const float* __restrict__ Wo,
                             const float* __restrict__ Wp)
{
    int i = blockIdx.x * blockDim.x + threadIdx.x;
    if (i < PE_N) { g_peh[i] = __float2half_rn(pe[i]); return; }
    int j = i - PE_N;
    if (j >= 5 * DD * DD) return;
    int w = j >> 20, o = j & (DD*DD - 1);
    const float* src = (w == 0) ? Wq : (w == 1) ? Wk : (w == 2) ? Wv
                     : (w == 3) ? Wo : Wp;
    if (w == 2)      { g_Wvh[o] = __float2half_rn(src[o]); }
    else if (w == 3) { g_Woh[o] = __float2half_rn(src[o]); }
    else {
        __half* dh = (w == 0) ? g_Wqh : (w == 1) ? g_Wkh : g_Wph;
        __half* dl = (w == 0) ? g_Wql : (w == 1) ? g_Wkl : g_Wpl;
        split2h(src[o], dh[o], dl[o]);
    }
}

// ---------------- Q / K / P projections (two-term), merged launch ------------
__global__ void __launch_bounds__(256, 2)
k_projQKP(const float* __restrict__ bu, const float* __restrict__ bv)
{
    const int z = blockIdx.z;                     // 0:Q  1:K  2:P
    if (z == 2 && blockIdx.y >= 16) return;       // P has 16 row tiles
    hp Ah = (z == 2) ? g_peh : g_hsh;
    const int M = (z == 2) ? PP : MHS;
    hp Wh = (z == 0) ? g_Wqh : (z == 1) ? g_Wkh : g_Wph;
    hp Wl = (z == 0) ? g_Wql : (z == 1) ? g_Wkl : g_Wpl;
    const int row0 = blockIdx.y * 128, col0 = blockIdx.x * 128;
    float acc[2][8][4] = {};
    hmma_main<3>(Ah, M, Wh, Wl, DD, DD, row0, col0, acc);
    EPI_DECLS
    #pragma unroll
    for (int i = 0; i < 2; i++)
        #pragma unroll
        for (int j = 0; j < 8; j++)
            #pragma unroll
            for (int r = 0; r < 4; r++) {
                int m = row0 + EPI_ROW(i, r);
                int n = col0 + EPI_COL(j, r);
                int h = n >> 7, d = n & 127;
                float v = acc[i][j][r];
                if (z == 0) {
                    int b = m >> 10, t = m & 1023;
                    size_t idx = ((size_t)(b*HH + h)*TT + t)*DKK + d;
                    g_quh[idx] = __float2half_rn(v + bu[h*DKK + d]);
                    g_qvh[idx] = __float2half_rn(v + bv[h*DKK + d]);
                } else if (z == 1) {
                    int b = m >> 10, t = m & 1023;
                    size_t idx = ((size_t)(b*HH + h)*TT + t)*DKK + d;
                    split2h(v, g_kh[idx], g_kl[idx]);
                } else {
                    if (m < PP) {
                        size_t idx = ((size_t)h*PP + m)*DKK + d;
                        split2h(v, g_ph[idx], g_pl[idx]);
                    }
                }
            }
}

// ---------------- V projection (one-term), transposed store ------------------
__global__ void __launch_bounds__(256, 2) k_projV()
{
    const int row0 = blockIdx.y * 128, col0 = blockIdx.x * 128;
    float acc[2][8][4] = {};
    hmma_main<2>(g_hsh, MHS, g_Wvh, (hp)0, DD, DD, row0, col0, acc);
    EPI_DECLS
    #pragma unroll
    for (int i = 0; i < 2; i++)
        #pragma unroll
        for (int j = 0; j < 8; j++)
            #pragma unroll
            for (int r = 0; r < 4; r++) {
                int m = row0 + EPI_ROW(i, r);
                int n = col0 + EPI_COL(j, r);
                int b = m >> 10, t = m & 1023;
                int h = n >> 7,  d = n & 127;
                size_t it = ((size_t)(b*HH + h)*DKK + d)*TT + t;  // (b,h,d,t)
                g_vTh[it] = __float2half_rn(acc[i][j][r]);
            }
}

// ---------------- AC: scores = qu @ k^T per (b,h) ---------------------------
__global__ void __launch_bounds__(256, 2) k_ac()
{
    const int bh = blockIdx.z;
    const size_t ob = (size_t)bh * TT * DKK;
    const int row0 = blockIdx.y * 128, col0 = blockIdx.x * 128;
    float acc[2][8][4] = {};
    hmma_main<3>(g_quh + ob, TT, g_kh + ob, g_kl + ob, TT, DKK, row0, col0, acc);
    EPI_DECLS
    float* C = g_scores + (size_t)bh * TT * TT;
    #pragma unroll
    for (int i = 0; i < 2; i++)
        #pragma unroll
        for (int j = 0; j < 8; j++)
            #pragma unroll
            for (int r = 0; r < 4; r++) {
                int m = row0 + EPI_ROW(i, r);
                int n = col0 + EPI_COL(j, r);
                C[(size_t)m * TT + n] = acc[i][j][r];
            }
}

// ---------------- BD: scores[m, n+m-1023] += qv @ p^T (rel-shift fused) -----
// exact diagonal band: col tile index cx = bx + 7 - my  (cx+my in [7,15])
__global__ void __launch_bounds__(256, 2) k_bd()
{
    const int bh = blockIdx.z, h = bh & 7;
    const int my = blockIdx.y;
    const int cx = blockIdx.x + 7 - my;
    const int row0 = my * 128, col0 = cx * 128;
    const size_t oa = (size_t)bh * TT * DKK;
    const size_t op = (size_t)h * PP * DKK;
    float acc[2][8][4] = {};
    hmma_main<3>(g_qvh + oa, TT, g_ph + op, g_pl + op, PP, DKK, row0, col0, acc);
    EPI_DECLS
    float* C = g_scores + (size_t)bh * TT * TT;
    #pragma unroll
    for (int i = 0; i < 2; i++)
        #pragma unroll
        for (int j = 0; j < 8; j++)
            #pragma unroll
            for (int r = 0; r < 4; r++) {
                int m = row0 + EPI_ROW(i, r);
                int n = col0 + EPI_COL(j, r);
                if (n < PP) {
                    int k = n + m - 1023;
                    if ((unsigned)k < (unsigned)TT)
                        C[(size_t)m * TT + k] += acc[i][j][r];
                }
            }
}

// ---------------- softmax: warp-per-row, shuffle-only reductions -------------
__global__ void k_softmax()
{
    const int row  = blockIdx.x * 8 + (threadIdx.x >> 5);
    const int lane = threadIdx.x & 31;
    const size_t rowoff = (size_t)row * TT;
    const float4* r4 = reinterpret_cast<const float4*>(g_scores + rowoff);
    const float s = 0.08838834764831845f;        // 1/sqrt(128)

    float4 v[8];
    float m = -1e30f;
    #pragma unroll
    for (int i = 0; i < 8; i++) {
        v[i] = r4[i * 32 + lane];
        v[i].x *= s; v[i].y *= s; v[i].z *= s; v[i].w *= s;
        m = fmaxf(m, fmaxf(fmaxf(v[i].x, v[i].y), fmaxf(v[i].z, v[i].w)));
    }
    #pragma unroll
    for (int o = 16; o > 0; o >>= 1) m = fmaxf(m, __shfl_xor_sync(~0u, m, o));

    float sum = 0.f;
    #pragma unroll
    for (int i = 0; i < 8; i++) {
        v[i].x = __expf(v[i].x - m); v[i].y = __expf(v[i].y - m);
        v[i].z = __expf(v[i].z - m); v[i].w = __expf(v[i].w - m);
        sum += (v[i].x + v[i].y) + (v[i].z + v[i].w);
    }
    #pragma unroll
    for (int o = 16; o > 0; o >>= 1) sum += __shfl_xor_sync(~0u, sum, o);

    float inv = __frcp_rn(sum);
    uint2* dst = reinterpret_cast<uint2*>(g_ath + rowoff);
    #pragma unroll
    for (int i = 0; i < 8; i++) {
        __half2 p01 = __floats2half2_rn(v[i].x * inv, v[i].y * inv);
        __half2 p23 = __floats2half2_rn(v[i].z * inv, v[i].w * inv);
        uint2 pk;
        pk.x = *reinterpret_cast<uint32_t*>(&p01);
        pk.y = *reinterpret_cast<uint32_t*>(&p23);
        dst[i * 32 + lane] = pk;
    }
}

// ---------------- AV: o = attn @ v per (b,h)  (one-term) --------------------
__global__ void __launch_bounds__(256, 2) k_av()
{
    const int bh = blockIdx.z, b = bh >> 3, h = bh & 7;
    const size_t oa = (size_t)bh * TT * TT;
    const size_t ov = (size_t)bh * DKK * TT;
    const int row0 = blockIdx.y * 128;
    float acc[2][8][4] = {};
    hmma_main<2>(g_ath + oa, TT, g_vTh + ov, (hp)0, DKK, TT, row0, 0, acc);
    EPI_DECLS
    #pragma unroll
    for (int i = 0; i < 2; i++)
        #pragma unroll
        for (int j = 0; j < 8; j++)
            #pragma unroll
            for (int r = 0; r < 4; r++) {
                int m = row0 + EPI_ROW(i, r);
                int n = EPI_COL(j, r);              // head-dim 0..127
                size_t idx = ((size_t)(b*TT + m)*HH + h)*DKK + n; // (b,t,h,d)
                g_oh[idx] = __float2half_rn(acc[i][j][r]);
            }
}

// ---------------- output projection (one-term) -------------------------------
__global__ void __launch_bounds__(256, 2) k_out(float* __restrict__ out)
{
    const int row0 = blockIdx.y * 128, col0 = blockIdx.x * 128;
    float acc[2][8][4] = {};
    hmma_main<2>(g_oh, MHS, g_Woh, (hp)0, DD, DD, row0, col0, acc);
    EPI_DECLS
    #pragma unroll
    for (int i = 0; i < 2; i++)
        #pragma unroll
        for (int j = 0; j < 8; j++)
            #pragma unroll
            for (int r = 0; r < 4; r++) {
                int m = row0 + EPI_ROW(i, r);
                int n = col0 + EPI_COL(j, r);
                out[(size_t)m * DD + n] = acc[i][j][r];
            }
}

// ---------------- launch ----------------------------------------------------
extern "C" void kernel_launch(void* const* d_in, const int* in_sizes, int n_in,
                              void* d_out, int out_size)
{
    const float* hs = (const float*)d_in[0];
    const float* pe = (const float*)d_in[1];
    const float* Wq = (const float*)d_in[2];
    const float* Wk = (const float*)d_in[3];
    const float* Wv = (const float*)d_in[4];
    const float* Wo = (const float*)d_in[5];
    const float* Wp = (const float*)d_in[6];
    const float* bu = (const float*)d_in[7];
    const float* bv = (const float*)d_in[8];
    float* out = (float*)d_out;

    static int attr_done = 0;
    if (!attr_done) {
        cudaFuncSetAttribute(k_projQKP, cudaFuncAttributeMaxDynamicSharedMemorySize, DYN3);
        cudaFuncSetAttribute(k_projV,   cudaFuncAttributeMaxDynamicSharedMemorySize, DYN2);
        cudaFuncSetAttribute(k_ac,      cudaFuncAttributeMaxDynamicSharedMemorySize, DYN3);
        cudaFuncSetAttribute(k_bd,      cudaFuncAttributeMaxDynamicSharedMemorySize, DYN3);
        cudaFuncSetAttribute(k_av,      cudaFuncAttributeMaxDynamicSharedMemorySize, DYN2);
        cudaFuncSetAttribute(k_out,     cudaFuncAttributeMaxDynamicSharedMemorySize, DYN2);
        attr_done = 1;
    }

    // launch order keeps k_bd at position 6 so ncu (-s 5 -c 1) profiles it
    k_split_hs  <<<(MHS*DD + 255)/256, 256>>>(hs);
    k_split_rest<<<(PE_N + 5*DD*DD + 255)/256, 256>>>(pe, Wq, Wk, Wv, Wo, Wp);

    k_projQKP<<<dim3(8, 32, 3), 256, DYN3>>>(bu, bv);
    k_projV  <<<dim3(8, 32),    256, DYN2>>>();
    k_ac <<<dim3(8, 8, BATCH*HH), 256, DYN3>>>();
    k_bd <<<dim3(9, 8, BATCH*HH), 256, DYN3>>>();
    k_softmax<<<BATCH*HH*TT/8, 256>>>();
    k_av <<<dim3(1, 8, BATCH*HH), 256, DYN2>>>();
    k_out<<<dim3(8, 32),    256, DYN2>>>(out);
}

// round 12
// speedup vs baseline: 2.0033x; 1.0028x over previous
#include <cuda_runtime.h>
#include <cuda_fp16.h>
#include <stdint.h>

#define BATCH 4
#define TT    1024
#define DD    1024
#define HH    8
#define DKK   128
#define PP    2047
#define MHS   (BATCH*TT)
#define BK    32
#define ROWP  40                        // padded smem row stride (halves)
#define BUFA  (128*ROWP)                // A buffer: 128 rows
#define BUFB  (64*ROWP)                 // B buffer: 64 rows
#define STAGES 3
#define STG3  (BUFA + 2*BUFB)           // halves per stage, two-term
#define STG2  (BUFA + BUFB)             // halves per stage, one-term
#define DYN3  (STAGES*STG3*2)           // 61440 B
#define DYN2  (STAGES*STG2*2)           // 46080 B
#define PE_N  (PP*DD)

// ---------------- scratch (device globals) -----------------------------------
__device__ __half g_hsh[MHS*DD];
__device__ __half g_peh[PE_N];
__device__ __half g_Wqh[DD*DD], g_Wql[DD*DD];
__device__ __half g_Wkh[DD*DD], g_Wkl[DD*DD];
__device__ __half g_Wvh[DD*DD];                     // one-term
__device__ __half g_Woh[DD*DD];                     // one-term
__device__ __half g_Wph[DD*DD], g_Wpl[DD*DD];
__device__ __half g_quh[BATCH*HH*TT*DKK];           // A-side
__device__ __half g_qvh[BATCH*HH*TT*DKK];           // A-side
__device__ __half g_kh [BATCH*HH*TT*DKK], g_kl [BATCH*HH*TT*DKK];
__device__ __half g_vTh[BATCH*HH*DKK*TT];           // (b,h,d,t) one-term
__device__ __half g_ph [HH*PP*DKK],       g_pl [HH*PP*DKK];
__device__ __half g_ath[(size_t)BATCH*HH*TT*TT];    // A-side probs
__device__ __half g_oh [MHS*DD];                    // A-side
__device__ float g_scores[(size_t)BATCH*HH*TT*TT];  // 134 MB fp32

typedef const __half* hp;

// ---------------- helpers ---------------------------------------------------
__device__ __forceinline__ void split2h(float x, __half& h, __half& l)
{
    h = __float2half_rn(x);
    l = __float2half_rn(x - __half2float(h));
}

__device__ __forceinline__ uint32_t cvta_s(const void* p)
{
    uint32_t a;
    asm("{ .reg .u64 t; cvta.to.shared.u64 t, %1; cvt.u32.u64 %0, t; }" : "=r"(a) : "l"(p));
    return a;
}

#define MMA_F16(D, A, B0, B1)                                              \
    asm volatile("mma.sync.aligned.m16n8k16.row.col.f32.f16.f16.f32 "      \
                 "{%0,%1,%2,%3}, {%4,%5,%6,%7}, {%8,%9}, {%0,%1,%2,%3};"   \
                 : "+f"(D[0]), "+f"(D[1]), "+f"(D[2]), "+f"(D[3])          \
                 : "r"(A[0]), "r"(A[1]), "r"(A[2]), "r"(A[3]),             \
                   "r"(B0), "r"(B1))

#define LDSM4(R, addr)                                                          \
    asm volatile("ldmatrix.sync.aligned.m8n8.x4.shared.b16 {%0,%1,%2,%3}, [%4];"\
                 : "=r"((R)[0]), "=r"((R)[1]), "=r"((R)[2]), "=r"((R)[3])       \
                 : "r"(addr))

// ---------------- async stage loader ----------------------------------------
// A: 128 rows x BK (512 16B-chunks), B buffers: 64 rows x BK (256 chunks each)
template<int NBUF>
__device__ __forceinline__ void load_stage(__half* sm, int s,
    hp Ah, int M, hp Bh, hp Bl, int N, int K, int row0, int col0, int k0)
{
    __half* st = sm + s * ((NBUF == 3) ? STG3 : STG2);
    const int tid = threadIdx.x;
    #pragma unroll
    for (int t = 0; t < 2; t++) {
        int slot = tid + t * 256;              // 0..511
        int r = slot >> 2, seg = slot & 3;
        int g = row0 + r;
        int ok = (g < M);
        const __half* sp = Ah + (size_t)(ok ? g : 0) * K + k0 + seg * 8;
        uint32_t d = cvta_s(st + r * ROWP + seg * 8);
        asm volatile("cp.async.cg.shared.global [%0], [%1], 16, %2;"
                     :: "r"(d), "l"(sp), "r"(ok ? 16 : 0) : "memory");
    }
    {
        int r = tid >> 2, seg = tid & 3;       // 0..63 rows
        int g = col0 + r;
        int ok = (g < N);
        const __half* sp = Bh + (size_t)(ok ? g : 0) * K + k0 + seg * 8;
        uint32_t d = cvta_s(st + BUFA + r * ROWP + seg * 8);
        asm volatile("cp.async.cg.shared.global [%0], [%1], 16, %2;"
                     :: "r"(d), "l"(sp), "r"(ok ? 16 : 0) : "memory");
        if (NBUF == 3) {
            const __half* sp2 = Bl + (size_t)(ok ? g : 0) * K + k0 + seg * 8;
            uint32_t d2 = cvta_s(st + BUFA + BUFB + r * ROWP + seg * 8);
            asm volatile("cp.async.cg.shared.global [%0], [%1], 16, %2;"
                         :: "r"(d2), "l"(sp2), "r"(ok ? 16 : 0) : "memory");
        }
    }
}

// ---------------- NT mainloop: C(128x64) = A(MxK) * (Bhi[+Blo])(NxK)^T -------
// 256 threads, 8 warps (4x2), warp tile 32x32, BK=32, cp.async 3-stage.
template<int NBUF>
__device__ __forceinline__ void hmma_main(
    hp Ah, int M, hp Bh, hp Bl, int N,
    int K, int row0, int col0, float acc[2][4][4])
{
    extern __shared__ __half smv[];
    const int stageh = (NBUF == 3) ? STG3 : STG2;
    const int tid = threadIdx.x, lane = tid & 31, warp = tid >> 5;
    const int wm = warp >> 1, wn = warp & 1;
    const int mi = lane >> 3, lr8 = lane & 7;
    const int row_off = (mi & 1) * 8 + lr8;
    const int col_off = (mi >> 1) * 8;

    const int niter = K >> 5;
    load_stage<NBUF>(smv, 0, Ah, M, Bh, Bl, N, K, row0, col0, 0);
    asm volatile("cp.async.commit_group;" ::: "memory");
    if (niter > 1) {
        load_stage<NBUF>(smv, 1, Ah, M, Bh, Bl, N, K, row0, col0, 32);
    }
    asm volatile("cp.async.commit_group;" ::: "memory");

    for (int it = 0; it < niter; it++) {
        if (it + 2 < niter) {
            load_stage<NBUF>(smv, (it + 2) % STAGES, Ah, M, Bh, Bl, N, K,
                             row0, col0, (it + 2) << 5);
            asm volatile("cp.async.commit_group;" ::: "memory");
            asm volatile("cp.async.wait_group 2;" ::: "memory");
        } else if (it + 1 < niter) {
            asm volatile("cp.async.wait_group 1;" ::: "memory");
        } else {
            asm volatile("cp.async.wait_group 0;" ::: "memory");
        }
        __syncthreads();

        const __half* st = smv + (it % STAGES) * stageh;
        #pragma unroll
        for (int kb = 0; kb < BK; kb += 16) {
            uint32_t a[2][4];
            #pragma unroll
            for (int i = 0; i < 2; i++) {
                int off = (wm * 32 + i * 16 + row_off) * ROWP + kb + col_off;
                LDSM4(a[i], cvta_s(st + off));
            }
            uint32_t bh4[2][4];
            #pragma unroll
            for (int g = 0; g < 2; g++) {
                int off = (wn * 32 + g * 16 + row_off) * ROWP + kb + col_off;
                LDSM4(bh4[g], cvta_s(st + BUFA + off));
            }
            if (NBUF == 3) {
                uint32_t bl4[2][4];
                #pragma unroll
                for (int g = 0; g < 2; g++) {
                    int off = (wn * 32 + g * 16 + row_off) * ROWP + kb + col_off;
                    LDSM4(bl4[g], cvta_s(st + BUFA + BUFB + off));
                }
                #pragma unroll
                for (int g = 0; g < 2; g++) {
                    MMA_F16(acc[0][g*2],   a[0], bh4[g][0], bh4[g][2]);
                    MMA_F16(acc[1][g*2],   a[1], bh4[g][0], bh4[g][2]);
                    MMA_F16(acc[0][g*2+1], a[0], bh4[g][1], bh4[g][3]);
                    MMA_F16(acc[1][g*2+1], a[1], bh4[g][1], bh4[g][3]);
                }
                #pragma unroll
                for (int g = 0; g < 2; g++) {
                    MMA_F16(acc[0][g*2],   a[0], bl4[g][0], bl4[g][2]);
                    MMA_F16(acc[1][g*2],   a[1], bl4[g][0], bl4[g][2]);
                    MMA_F16(acc[0][g*2+1], a[0], bl4[g][1], bl4[g][3]);
                    MMA_F16(acc[1][g*2+1], a[1], bl4[g][1], bl4[g][3]);
                }
            } else {
                #pragma unroll
                for (int g = 0; g < 2; g++) {
                    MMA_F16(acc[0][g*2],   a[0], bh4[g][0], bh4[g][2]);
                    MMA_F16(acc[1][g*2],   a[1], bh4[g][0], bh4[g][2]);
                    MMA_F16(acc[0][g*2+1], a[0], bh4[g][1], bh4[g][3]);
                    MMA_F16(acc[1][g*2+1], a[1], bh4[g][1], bh4[g][3]);
                }
            }
        }
        __syncthreads();
    }
}

// epilogue coordinate helpers (warp tile 32x32)
#define EPI_ROW(i, r)  (wm*32 + (i)*16 + grp + ((r) >> 1)*8)
#define EPI_COL(j, r)  (wn*32 + (j)*8 + qid*2 + ((r) & 1))
#define EPI_DECLS                                          \
    const int lane = threadIdx.x & 31;                     \
    const int warp = threadIdx.x >> 5;                     \
    const int grp = lane >> 2, qid = lane & 3;             \
    const int wm = warp >> 1, wn = warp & 1;

// ---------------- splits -----------------------------------------------------
__global__ void k_split_hs(const float* __restrict__ hs)
{
    int i = blockIdx.x * blockDim.x + threadIdx.x;
    if (i < MHS*DD) g_hsh[i] = __float2half_rn(hs[i]);
}

__global__ void k_split_rest(const float* __restrict__ pe,
                             const float* __restrict__ Wq,
                             const float* __restrict__ Wk,
                             const float* __restrict__ Wv,
                             const float* __restrict__ Wo,
                             const float* __restrict__ Wp)
{
    int i = blockIdx.x * blockDim.x + threadIdx.x;
    if (i < PE_N) { g_peh[i] = __float2half_rn(pe[i]); return; }
    int j = i - PE_N;
    if (j >= 5 * DD * DD) return;
    int w = j >> 20, o = j & (DD*DD - 1);
    const float* src = (w == 0) ? Wq : (w == 1) ? Wk : (w == 2) ? Wv
                     : (w == 3) ? Wo : Wp;
    if (w == 2)      { g_Wvh[o] = __float2half_rn(src[o]); }
    else if (w == 3) { g_Woh[o] = __float2half_rn(src[o]); }
    else {
        __half* dh = (w == 0) ? g_Wqh : (w == 1) ? g_Wkh : g_Wph;
        __half* dl = (w == 0) ? g_Wql : (w == 1) ? g_Wkl : g_Wpl;
        split2h(src[o], dh[o], dl[o]);
    }
}

// ---------------- Q / K / P projections (two-term), merged launch ------------
__global__ void __launch_bounds__(256, 3)
k_projQKP(const float* __restrict__ bu, const float* __restrict__ bv)
{
    const int z = blockIdx.z;                     // 0:Q  1:K  2:P
    if (z == 2 && blockIdx.y >= 16) return;       // P has 16 row tiles
    hp Ah = (z == 2) ? g_peh : g_hsh;
    const int M = (z == 2) ? PP : MHS;
    hp Wh = (z == 0) ? g_Wqh : (z == 1) ? g_Wkh : g_Wph;
    hp Wl = (z == 0) ? g_Wql : (z == 1) ? g_Wkl : g_Wpl;
    const int row0 = blockIdx.y * 128, col0 = blockIdx.x * 64;
    float acc[2][4][4] = {};
    hmma_main<3>(Ah, M, Wh, Wl, DD, DD, row0, col0, acc);
    EPI_DECLS
    #pragma unroll
    for (int i = 0; i < 2; i++)
        #pragma unroll
        for (int j = 0; j < 4; j++)
            #pragma unroll
            for (int r = 0; r < 4; r++) {
                int m = row0 + EPI_ROW(i, r);
                int n = col0 + EPI_COL(j, r);
                int h = n >> 7, d = n & 127;
                float v = acc[i][j][r];
                if (z == 0) {
                    int b = m >> 10, t = m & 1023;
                    size_t idx = ((size_t)(b*HH + h)*TT + t)*DKK + d;
                    g_quh[idx] = __float2half_rn(v + bu[h*DKK + d]);
                    g_qvh[idx] = __float2half_rn(v + bv[h*DKK + d]);
                } else if (z == 1) {
                    int b = m >> 10, t = m & 1023;
                    size_t idx = ((size_t)(b*HH + h)*TT + t)*DKK + d;
                    split2h(v, g_kh[idx], g_kl[idx]);
                } else {
                    if (m < PP) {
                        size_t idx = ((size_t)h*PP + m)*DKK + d;
                        split2h(v, g_ph[idx], g_pl[idx]);
                    }
                }
            }
}

// ---------------- V projection (one-term), transposed store ------------------
__global__ void __launch_bounds__(256, 3) k_projV()
{
    const int row0 = blockIdx.y * 128, col0 = blockIdx.x * 64;
    float acc[2][4][4] = {};
    hmma_main<2>(g_hsh, MHS, g_Wvh, (hp)0, DD, DD, row0, col0, acc);
    EPI_DECLS
    #pragma unroll
    for (int i = 0; i < 2; i++)
        #pragma unroll
        for (int j = 0; j < 4; j++)
            #pragma unroll
            for (int r = 0; r < 4; r++) {
                int m = row0 + EPI_ROW(i, r);
                int n = col0 + EPI_COL(j, r);
                int b = m >> 10, t = m & 1023;
                int h = n >> 7,  d = n & 127;
                size_t it = ((size_t)(b*HH + h)*DKK + d)*TT + t;  // (b,h,d,t)
                g_vTh[it] = __float2half_rn(acc[i][j][r]);
            }
}

// ---------------- AC: scores = qu @ k^T per (b,h) ---------------------------
__global__ void __launch_bounds__(256, 3) k_ac()
{
    const int bh = blockIdx.z;
    const size_t ob = (size_t)bh * TT * DKK;
    const int row0 = blockIdx.y * 128, col0 = blockIdx.x * 64;
    float acc[2][4][4] = {};
    hmma_main<3>(g_quh + ob, TT, g_kh + ob, g_kl + ob, TT, DKK, row0, col0, acc);
    EPI_DECLS
    float* C = g_scores + (size_t)bh * TT * TT;
    #pragma unroll
    for (int i = 0; i < 2; i++)
        #pragma unroll
        for (int j = 0; j < 4; j++)
            #pragma unroll
            for (int r = 0; r < 4; r++) {
                int m = row0 + EPI_ROW(i, r);
                int n = col0 + EPI_COL(j, r);
                C[(size_t)m * TT + n] = acc[i][j][r];
            }
}

// ---------------- BD: scores[m, n+m-1023] += qv @ p^T (rel-shift fused) -----
// exact diagonal band for 64-wide col tiles: 18 tiles per row tile
__global__ void __launch_bounds__(256, 3) k_bd()
{
    const int bh = blockIdx.z, h = bh & 7;
    const int my = blockIdx.y;
    int cxmin = 896 - 128 * my;                   // ceil((833-128my)/64) via +63
    cxmin = (cxmin > 0) ? (cxmin >> 6) : 0;
    const int cx = blockIdx.x + cxmin;
    const int row0 = my * 128, col0 = cx * 64;
    const size_t oa = (size_t)bh * TT * DKK;
    const size_t op = (size_t)h * PP * DKK;
    float acc[2][4][4] = {};
    hmma_main<3>(g_qvh + oa, TT, g_ph + op, g_pl + op, PP, DKK, row0, col0, acc);
    EPI_DECLS
    float* C = g_scores + (size_t)bh * TT * TT;
    #pragma unroll
    for (int i = 0; i < 2; i++)
        #pragma unroll
        for (int j = 0; j < 4; j++)
            #pragma unroll
            for (int r = 0; r < 4; r++) {
                int m = row0 + EPI_ROW(i, r);
                int n = col0 + EPI_COL(j, r);
                if (n < PP) {
                    int k = n + m - 1023;
                    if ((unsigned)k < (unsigned)TT)
                        C[(size_t)m * TT + k] += acc[i][j][r];
                }
            }
}

// ---------------- softmax: warp-per-row, shuffle-only reductions -------------
__global__ void k_softmax()
{
    const int row  = blockIdx.x * 8 + (threadIdx.x >> 5);
    const int lane = threadIdx.x & 31;
    const size_t rowoff = (size_t)row * TT;
    const float4* r4 = reinterpret_cast<const float4*>(g_scores + rowoff);
    const float s = 0.08838834764831845f;        // 1/sqrt(128)

    float4 v[8];
    float m = -1e30f;
    #pragma unroll
    for (int i = 0; i < 8; i++) {
        v[i] = r4[i * 32 + lane];
        v[i].x *= s; v[i].y *= s; v[i].z *= s; v[i].w *= s;
        m = fmaxf(m, fmaxf(fmaxf(v[i].x, v[i].y), fmaxf(v[i].z, v[i].w)));
    }
    #pragma unroll
    for (int o = 16; o > 0; o >>= 1) m = fmaxf(m, __shfl_xor_sync(~0u, m, o));

    float sum = 0.f;
    #pragma unroll
    for (int i = 0; i < 8; i++) {
        v[i].x = __expf(v[i].x - m); v[i].y = __expf(v[i].y - m);
        v[i].z = __expf(v[i].z - m); v[i].w = __expf(v[i].w - m);
        sum += (v[i].x + v[i].y) + (v[i].z + v[i].w);
    }
    #pragma unroll
    for (int o = 16; o > 0; o >>= 1) sum += __shfl_xor_sync(~0u, sum, o);

    float inv = __frcp_rn(sum);
    uint2* dst = reinterpret_cast<uint2*>(g_ath + rowoff);
    #pragma unroll
    for (int i = 0; i < 8; i++) {
        __half2 p01 = __floats2half2_rn(v[i].x * inv, v[i].y * inv);
        __half2 p23 = __floats2half2_rn(v[i].z * inv, v[i].w * inv);
        uint2 pk;
        pk.x = *reinterpret_cast<uint32_t*>(&p01);
        pk.y = *reinterpret_cast<uint32_t*>(&p23);
        dst[i * 32 + lane] = pk;
    }
}

// ---------------- AV: o = attn @ v per (b,h)  (one-term) --------------------
__global__ void __launch_bounds__(256, 3) k_av()
{
    const int bh = blockIdx.z, b = bh >> 3, h = bh & 7;
    const size_t oa = (size_t)bh * TT * TT;
    const size_t ov = (size_t)bh * DKK * TT;
    const int row0 = blockIdx.y * 128, col0 = blockIdx.x * 64;
    float acc[2][4][4] = {};
    hmma_main<2>(g_ath + oa, TT, g_vTh + ov, (hp)0, DKK, TT, row0, col0, acc);
    EPI_DECLS
    #pragma unroll
    for (int i = 0; i < 2; i++)
        #pragma unroll
        for (int j = 0; j < 4; j++)
            #pragma unroll
            for (int r = 0; r < 4; r++) {
                int m = row0 + EPI_ROW(i, r);
                int n = col0 + EPI_COL(j, r);       // head-dim 0..127
                size_t idx = ((size_t)(b*TT + m)*HH + h)*DKK + n; // (b,t,h,d)
                g_oh[idx] = __float2half_rn(acc[i][j][r]);
            }
}

// ---------------- output projection (one-term) -------------------------------
__global__ void __launch_bounds__(256, 3) k_out(float* __restrict__ out)
{
    const int row0 = blockIdx.y * 128, col0 = blockIdx.x * 64;
    float acc[2][4][4] = {};
    hmma_main<2>(g_oh, MHS, g_Woh, (hp)0, DD, DD, row0, col0, acc);
    EPI_DECLS
    #pragma unroll
    for (int i = 0; i < 2; i++)
        #pragma unroll
        for (int j = 0; j < 4; j++)
            #pragma unroll
            for (int r = 0; r < 4; r++) {
                int m = row0 + EPI_ROW(i, r);
                int n = col0 + EPI_COL(j, r);
                out[(size_t)m * DD + n] = acc[i][j][r];
            }
}

// ---------------- launch ----------------------------------------------------
extern "C" void kernel_launch(void* const* d_in, const int* in_sizes, int n_in,
                              void* d_out, int out_size)
{
    const float* hs = (const float*)d_in[0];
    const float* pe = (const float*)d_in[1];
    const float* Wq = (const float*)d_in[2];
    const float* Wk = (const float*)d_in[3];
    const float* Wv = (const float*)d_in[4];
    const float* Wo = (const float*)d_in[5];
    const float* Wp = (const float*)d_in[6];
    const float* bu = (const float*)d_in[7];
    const float* bv = (const float*)d_in[8];
    float* out = (float*)d_out;

    static int attr_done = 0;
    if (!attr_done) {
        cudaFuncSetAttribute(k_projQKP, cudaFuncAttributeMaxDynamicSharedMemorySize, DYN3);
        cudaFuncSetAttribute(k_projV,   cudaFuncAttributeMaxDynamicSharedMemorySize, DYN2);
        cudaFuncSetAttribute(k_ac,      cudaFuncAttributeMaxDynamicSharedMemorySize, DYN3);
        cudaFuncSetAttribute(k_bd,      cudaFuncAttributeMaxDynamicSharedMemorySize, DYN3);
        cudaFuncSetAttribute(k_av,      cudaFuncAttributeMaxDynamicSharedMemorySize, DYN2);
        cudaFuncSetAttribute(k_out,     cudaFuncAttributeMaxDynamicSharedMemorySize, DYN2);
        attr_done = 1;
    }

    // launch order keeps k_bd at position 6 so ncu (-s 5 -c 1) profiles it
    k_split_hs  <<<(MHS*DD + 255)/256, 256>>>(hs);
    k_split_rest<<<(PE_N + 5*DD*DD + 255)/256, 256>>>(pe, Wq, Wk, Wv, Wo, Wp);

    k_projQKP<<<dim3(16, 32, 3), 256, DYN3>>>(bu, bv);
    k_projV  <<<dim3(16, 32),    256, DYN2>>>();
    k_ac <<<dim3(16, 8, BATCH*HH), 256, DYN3>>>();
    k_bd <<<dim3(18, 8, BATCH*HH), 256, DYN3>>>();
    k_softmax<<<BATCH*HH*TT/8, 256>>>();
    k_av <<<dim3(2, 8, BATCH*HH), 256, DYN2>>>();
    k_out<<<dim3(16, 32),    256, DYN2>>>(out);
}

// round 13
// speedup vs baseline: 2.3759x; 1.1860x over previous
#include <cuda_runtime.h>
#include <cuda_fp16.h>
#include <stdint.h>

#define BATCH 4
#define TT    1024
#define DD    1024
#define HH    8
#define DKK   128
#define PP    2047
#define MHS   (BATCH*TT)
#define BK    32
#define ROWP  40                        // padded smem row stride (halves)
#define BUFA  (128*ROWP)                // A buffer: 128 rows
#define BUFB  (64*ROWP)                 // B buffer: 64 rows
#define STAGES 3
#define STG   (BUFA + BUFB)             // halves per stage
#define DYN   (STAGES*STG*2)            // 46080 B
#define PE_N  (PP*DD)

// ---------------- scratch (device globals; all one-term fp16) ----------------
__device__ __half g_hsh[MHS*DD];
__device__ __half g_peh[PE_N];
__device__ __half g_Wqh[DD*DD], g_Wkh[DD*DD], g_Wvh[DD*DD];
__device__ __half g_Woh[DD*DD], g_Wph[DD*DD];
__device__ __half g_quh[BATCH*HH*TT*DKK];
__device__ __half g_qvh[BATCH*HH*TT*DKK];
__device__ __half g_kh [BATCH*HH*TT*DKK];
__device__ __half g_vTh[BATCH*HH*DKK*TT];           // (b,h,d,t)
__device__ __half g_ph [HH*PP*DKK];
__device__ __half g_ath[(size_t)BATCH*HH*TT*TT];    // probs
__device__ __half g_oh [MHS*DD];
__device__ float g_scores[(size_t)BATCH*HH*TT*TT];  // 134 MB fp32

typedef const __half* hp;

// ---------------- helpers ---------------------------------------------------
__device__ __forceinline__ uint32_t cvta_s(const void* p)
{
    uint32_t a;
    asm("{ .reg .u64 t; cvta.to.shared.u64 t, %1; cvt.u32.u64 %0, t; }" : "=r"(a) : "l"(p));
    return a;
}

#define MMA_F16(D, A, B0, B1)                                              \
    asm volatile("mma.sync.aligned.m16n8k16.row.col.f32.f16.f16.f32 "      \
                 "{%0,%1,%2,%3}, {%4,%5,%6,%7}, {%8,%9}, {%0,%1,%2,%3};"   \
                 : "+f"(D[0]), "+f"(D[1]), "+f"(D[2]), "+f"(D[3])          \
                 : "r"(A[0]), "r"(A[1]), "r"(A[2]), "r"(A[3]),             \
                   "r"(B0), "r"(B1))

#define LDSM4(R, addr)                                                          \
    asm volatile("ldmatrix.sync.aligned.m8n8.x4.shared.b16 {%0,%1,%2,%3}, [%4];"\
                 : "=r"((R)[0]), "=r"((R)[1]), "=r"((R)[2]), "=r"((R)[3])       \
                 : "r"(addr))

// ---------------- async stage loader ----------------------------------------
// A: 128 rows x BK (512 16B-chunks), B: 64 rows x BK (256 chunks)
__device__ __forceinline__ void load_stage(__half* sm, int s,
    hp Ah, int M, hp Bh, int N, int K, int row0, int col0, int k0)
{
    __half* st = sm + s * STG;
    const int tid = threadIdx.x;
    #pragma unroll
    for (int t = 0; t < 2; t++) {
        int slot = tid + t * 256;              // 0..511
        int r = slot >> 2, seg = slot & 3;
        int g = row0 + r;
        int ok = (g < M);
        const __half* sp = Ah + (size_t)(ok ? g : 0) * K + k0 + seg * 8;
        uint32_t d = cvta_s(st + r * ROWP + seg * 8);
        asm volatile("cp.async.cg.shared.global [%0], [%1], 16, %2;"
                     :: "r"(d), "l"(sp), "r"(ok ? 16 : 0) : "memory");
    }
    {
        int r = tid >> 2, seg = tid & 3;       // 0..63 rows
        int g = col0 + r;
        int ok = (g < N);
        const __half* sp = Bh + (size_t)(ok ? g : 0) * K + k0 + seg * 8;
        uint32_t d = cvta_s(st + BUFA + r * ROWP + seg * 8);
        asm volatile("cp.async.cg.shared.global [%0], [%1], 16, %2;"
                     :: "r"(d), "l"(sp), "r"(ok ? 16 : 0) : "memory");
    }
}

// ---------------- NT mainloop: C(128x64) = A(MxK) * B(NxK)^T -----------------
// 256 threads, 8 warps (4x2), warp tile 32x32, BK=32, cp.async 3-stage.
__device__ __forceinline__ void hmma_main(
    hp Ah, int M, hp Bh, int N,
    int K, int row0, int col0, float acc[2][4][4])
{
    extern __shared__ __half smv[];
    const int tid = threadIdx.x, lane = tid & 31, warp = tid >> 5;
    const int wm = warp >> 1, wn = warp & 1;
    const int mi = lane >> 3, lr8 = lane & 7;
    const int row_off = (mi & 1) * 8 + lr8;
    const int col_off = (mi >> 1) * 8;

    const int niter = K >> 5;
    load_stage(smv, 0, Ah, M, Bh, N, K, row0, col0, 0);
    asm volatile("cp.async.commit_group;" ::: "memory");
    if (niter > 1) {
        load_stage(smv, 1, Ah, M, Bh, N, K, row0, col0, 32);
    }
    asm volatile("cp.async.commit_group;" ::: "memory");

    for (int it = 0; it < niter; it++) {
        if (it + 2 < niter) {
            load_stage(smv, (it + 2) % STAGES, Ah, M, Bh, N, K,
                       row0, col0, (it + 2) << 5);
            asm volatile("cp.async.commit_group;" ::: "memory");
            asm volatile("cp.async.wait_group 2;" ::: "memory");
        } else if (it + 1 < niter) {
            asm volatile("cp.async.wait_group 1;" ::: "memory");
        } else {
            asm volatile("cp.async.wait_group 0;" ::: "memory");
        }
        __syncthreads();

        const __half* st = smv + (it % STAGES) * STG;
        #pragma unroll
        for (int kb = 0; kb < BK; kb += 16) {
            uint32_t a[2][4];
            #pragma unroll
            for (int i = 0; i < 2; i++) {
                int off = (wm * 32 + i * 16 + row_off) * ROWP + kb + col_off;
                LDSM4(a[i], cvta_s(st + off));
            }
            uint32_t b4[2][4];
            #pragma unroll
            for (int g = 0; g < 2; g++) {
                int off = (wn * 32 + g * 16 + row_off) * ROWP + kb + col_off;
                LDSM4(b4[g], cvta_s(st + BUFA + off));
            }
            #pragma unroll
            for (int g = 0; g < 2; g++) {
                MMA_F16(acc[0][g*2],   a[0], b4[g][0], b4[g][2]);
                MMA_F16(acc[1][g*2],   a[1], b4[g][0], b4[g][2]);
                MMA_F16(acc[0][g*2+1], a[0], b4[g][1], b4[g][3]);
                MMA_F16(acc[1][g*2+1], a[1], b4[g][1], b4[g][3]);
            }
        }
        __syncthreads();
    }
}

// epilogue coordinate helpers (warp tile 32x32)
#define EPI_ROW(i, r)  (wm*32 + (i)*16 + grp + ((r) >> 1)*8)
#define EPI_COL(j, r)  (wn*32 + (j)*8 + qid*2 + ((r) & 1))
#define EPI_DECLS                                          \
    const int lane = threadIdx.x & 31;                     \
    const int warp = threadIdx.x >> 5;                     \
    const int grp = lane >> 2, qid = lane & 3;             \
    const int wm = warp >> 1, wn = warp & 1;

// ---------------- splits (fp16 convert only) ---------------------------------
__global__ void k_split_hs(const float* __restrict__ hs)
{
    int i = blockIdx.x * blockDim.x + threadIdx.x;
    if (i < MHS*DD) g_hsh[i] = __float2half_rn(hs[i]);
}

__global__ void k_split_pe(const float* __restrict__ pe)
{
    int i = blockIdx.x * blockDim.x + threadIdx.x;
    if (i < PE_N) g_peh[i] = __float2half_rn(pe[i]);
}

__global__ void k_split_w(const float* __restrict__ Wq,
                          const float* __restrict__ Wk,
                          const float* __restrict__ Wv,
                          const float* __restrict__ Wo,
                          const float* __restrict__ Wp)
{
    int i = blockIdx.x * blockDim.x + threadIdx.x;
    if (i >= 5 * DD * DD) return;
    int w = i >> 20, o = i & (DD*DD - 1);
    const float* src = (w == 0) ? Wq : (w == 1) ? Wk : (w == 2) ? Wv
                     : (w == 3) ? Wo : Wp;
    __half* dst = (w == 0) ? g_Wqh : (w == 1) ? g_Wkh : (w == 2) ? g_Wvh
                : (w == 3) ? g_Woh : g_Wph;
    dst[o] = __float2half_rn(src[o]);
}

// ---------------- Q / K / P / V projections, single launch -------------------
__global__ void __launch_bounds__(256, 3)
k_proj(const float* __restrict__ bu, const float* __restrict__ bv)
{
    const int z = blockIdx.z;                     // 0:Q 1:K 2:P 3:V
    if (z == 2 && blockIdx.y >= 16) return;       // P has 16 row tiles
    hp Ah = (z == 2) ? g_peh : g_hsh;
    const int M = (z == 2) ? PP : MHS;
    hp Wh = (z == 0) ? g_Wqh : (z == 1) ? g_Wkh : (z == 2) ? g_Wph : g_Wvh;
    const int row0 = blockIdx.y * 128, col0 = blockIdx.x * 64;
    float acc[2][4][4] = {};
    hmma_main(Ah, M, Wh, DD, DD, row0, col0, acc);
    EPI_DECLS
    #pragma unroll
    for (int i = 0; i < 2; i++)
        #pragma unroll
        for (int j = 0; j < 4; j++)
            #pragma unroll
            for (int r = 0; r < 4; r++) {
                int m = row0 + EPI_ROW(i, r);
                int n = col0 + EPI_COL(j, r);
                int h = n >> 7, d = n & 127;
                float v = acc[i][j][r];
                if (z == 0) {
                    int b = m >> 10, t = m & 1023;
                    size_t idx = ((size_t)(b*HH + h)*TT + t)*DKK + d;
                    g_quh[idx] = __float2half_rn(v + bu[h*DKK + d]);
                    g_qvh[idx] = __float2half_rn(v + bv[h*DKK + d]);
                } else if (z == 1) {
                    int b = m >> 10, t = m & 1023;
                    size_t idx = ((size_t)(b*HH + h)*TT + t)*DKK + d;
                    g_kh[idx] = __float2half_rn(v);
                } else if (z == 2) {
                    if (m < PP) {
                        size_t idx = ((size_t)h*PP + m)*DKK + d;
                        g_ph[idx] = __float2half_rn(v);
                    }
                } else {
                    int b = m >> 10, t = m & 1023;
                    size_t it = ((size_t)(b*HH + h)*DKK + d)*TT + t;  // (b,h,d,t)
                    g_vTh[it] = __float2half_rn(v);
                }
            }
}

// ---------------- AC: scores = qu @ k^T per (b,h) ---------------------------
__global__ void __launch_bounds__(256, 3) k_ac()
{
    const int bh = blockIdx.z;
    const size_t ob = (size_t)bh * TT * DKK;
    const int row0 = blockIdx.y * 128, col0 = blockIdx.x * 64;
    float acc[2][4][4] = {};
    hmma_main(g_quh + ob, TT, g_kh + ob, TT, DKK, row0, col0, acc);
    EPI_DECLS
    float* C = g_scores + (size_t)bh * TT * TT;
    #pragma unroll
    for (int i = 0; i < 2; i++)
        #pragma unroll
        for (int j = 0; j < 4; j++)
            #pragma unroll
            for (int r = 0; r < 4; r++) {
                int m = row0 + EPI_ROW(i, r);
                int n = col0 + EPI_COL(j, r);
                C[(size_t)m * TT + n] = acc[i][j][r];
            }
}

// ---------------- BD: scores[m, n+m-1023] += qv @ p^T (rel-shift fused) -----
// exact diagonal band for 64-wide col tiles: 18 tiles per row tile
__global__ void __launch_bounds__(256, 3) k_bd()
{
    const int bh = blockIdx.z, h = bh & 7;
    const int my = blockIdx.y;
    int cxmin = 896 - 128 * my;
    cxmin = (cxmin > 0) ? (cxmin >> 6) : 0;
    const int cx = blockIdx.x + cxmin;
    const int row0 = my * 128, col0 = cx * 64;
    const size_t oa = (size_t)bh * TT * DKK;
    const size_t op = (size_t)h * PP * DKK;
    float acc[2][4][4] = {};
    hmma_main(g_qvh + oa, TT, g_ph + op, PP, DKK, row0, col0, acc);
    EPI_DECLS
    float* C = g_scores + (size_t)bh * TT * TT;
    #pragma unroll
    for (int i = 0; i < 2; i++)
        #pragma unroll
        for (int j = 0; j < 4; j++)
            #pragma unroll
            for (int r = 0; r < 4; r++) {
                int m = row0 + EPI_ROW(i, r);
                int n = col0 + EPI_COL(j, r);
                if (n < PP) {
                    int k = n + m - 1023;
                    if ((unsigned)k < (unsigned)TT)
                        C[(size_t)m * TT + k] += acc[i][j][r];
                }
            }
}

// ---------------- softmax: warp-per-row, shuffle-only reductions -------------
__global__ void k_softmax()
{
    const int row  = blockIdx.x * 8 + (threadIdx.x >> 5);
    const int lane = threadIdx.x & 31;
    const size_t rowoff = (size_t)row * TT;
    const float4* r4 = reinterpret_cast<const float4*>(g_scores + rowoff);
    const float s = 0.08838834764831845f;        // 1/sqrt(128)

    float4 v[8];
    float m = -1e30f;
    #pragma unroll
    for (int i = 0; i < 8; i++) {
        v[i] = r4[i * 32 + lane];
        v[i].x *= s; v[i].y *= s; v[i].z *= s; v[i].w *= s;
        m = fmaxf(m, fmaxf(fmaxf(v[i].x, v[i].y), fmaxf(v[i].z, v[i].w)));
    }
    #pragma unroll
    for (int o = 16; o > 0; o >>= 1) m = fmaxf(m, __shfl_xor_sync(~0u, m, o));

    float sum = 0.f;
    #pragma unroll
    for (int i = 0; i < 8; i++) {
        v[i].x = __expf(v[i].x - m); v[i].y = __expf(v[i].y - m);
        v[i].z = __expf(v[i].z - m); v[i].w = __expf(v[i].w - m);
        sum += (v[i].x + v[i].y) + (v[i].z + v[i].w);
    }
    #pragma unroll
    for (int o = 16; o > 0; o >>= 1) sum += __shfl_xor_sync(~0u, sum, o);

    float inv = __frcp_rn(sum);
    uint2* dst = reinterpret_cast<uint2*>(g_ath + rowoff);
    #pragma unroll
    for (int i = 0; i < 8; i++) {
        __half2 p01 = __floats2half2_rn(v[i].x * inv, v[i].y * inv);
        __half2 p23 = __floats2half2_rn(v[i].z * inv, v[i].w * inv);
        uint2 pk;
        pk.x = *reinterpret_cast<uint32_t*>(&p01);
        pk.y = *reinterpret_cast<uint32_t*>(&p23);
        dst[i * 32 + lane] = pk;
    }
}

// ---------------- AV: o = attn @ v per (b,h) --------------------------------
__global__ void __launch_bounds__(256, 3) k_av()
{
    const int bh = blockIdx.z, b = bh >> 3, h = bh & 7;
    const size_t oa = (size_t)bh * TT * TT;
    const size_t ov = (size_t)bh * DKK * TT;
    const int row0 = blockIdx.y * 128, col0 = blockIdx.x * 64;
    float acc[2][4][4] = {};
    hmma_main(g_ath + oa, TT, g_vTh + ov, DKK, TT, row0, col0, acc);
    EPI_DECLS
    #pragma unroll
    for (int i = 0; i < 2; i++)
        #pragma unroll
        for (int j = 0; j < 4; j++)
            #pragma unroll
            for (int r = 0; r < 4; r++) {
                int m = row0 + EPI_ROW(i, r);
                int n = col0 + EPI_COL(j, r);       // head-dim 0..127
                size_t idx = ((size_t)(b*TT + m)*HH + h)*DKK + n; // (b,t,h,d)
                g_oh[idx] = __float2half_rn(acc[i][j][r]);
            }
}

// ---------------- output projection ------------------------------------------
__global__ void __launch_bounds__(256, 3) k_out(float* __restrict__ out)
{
    const int row0 = blockIdx.y * 128, col0 = blockIdx.x * 64;
    float acc[2][4][4] = {};
    hmma_main(g_oh, MHS, g_Woh, DD, DD, row0, col0, acc);
    EPI_DECLS
    #pragma unroll
    for (int i = 0; i < 2; i++)
        #pragma unroll
        for (int j = 0; j < 4; j++)
            #pragma unroll
            for (int r = 0; r < 4; r++) {
                int m = row0 + EPI_ROW(i, r);
                int n = col0 + EPI_COL(j, r);
                out[(size_t)m * DD + n] = acc[i][j][r];
            }
}

// ---------------- launch ----------------------------------------------------
extern "C" void kernel_launch(void* const* d_in, const int* in_sizes, int n_in,
                              void* d_out, int out_size)
{
    const float* hs = (const float*)d_in[0];
    const float* pe = (const float*)d_in[1];
    const float* Wq = (const float*)d_in[2];
    const float* Wk = (const float*)d_in[3];
    const float* Wv = (const float*)d_in[4];
    const float* Wo = (const float*)d_in[5];
    const float* Wp = (const float*)d_in[6];
    const float* bu = (const float*)d_in[7];
    const float* bv = (const float*)d_in[8];
    float* out = (float*)d_out;

    static int attr_done = 0;
    if (!attr_done) {
        cudaFuncSetAttribute(k_proj, cudaFuncAttributeMaxDynamicSharedMemorySize, DYN);
        cudaFuncSetAttribute(k_ac,   cudaFuncAttributeMaxDynamicSharedMemorySize, DYN);
        cudaFuncSetAttribute(k_bd,   cudaFuncAttributeMaxDynamicSharedMemorySize, DYN);
        cudaFuncSetAttribute(k_av,   cudaFuncAttributeMaxDynamicSharedMemorySize, DYN);
        cudaFuncSetAttribute(k_out,  cudaFuncAttributeMaxDynamicSharedMemorySize, DYN);
        attr_done = 1;
    }

    // launch order keeps k_bd at position 6 so ncu (-s 5 -c 1) profiles it
    k_split_hs<<<(MHS*DD + 255)/256, 256>>>(hs);
    k_split_pe<<<(PE_N + 255)/256, 256>>>(pe);
    k_split_w <<<(5*DD*DD + 255)/256, 256>>>(Wq, Wk, Wv, Wo, Wp);

    k_proj<<<dim3(16, 32, 4), 256, DYN>>>(bu, bv);
    k_ac <<<dim3(16, 8, BATCH*HH), 256, DYN>>>();
    k_bd <<<dim3(18, 8, BATCH*HH), 256, DYN>>>();
    k_softmax<<<BATCH*HH*TT/8, 256>>>();
    k_av <<<dim3(2, 8, BATCH*HH), 256, DYN>>>();
    k_out<<<dim3(16, 32), 256, DYN>>>(out);
}